// round 5
// baseline (speedup 1.0000x reference)
#include <cuda_runtime.h>
#include <cuda_bf16.h>
#include <math_constants.h>
#include <cstdint>

// Problem constants
#define BB 2
#define SS 2048
#define DD 1024
#define HH 16
#define DK 64
#define FF 4096
#define MR (BB*SS)          // 4096 rows
#define QKVN 3072

// ---------------- scratch (static device globals: alloc-free rule) ----------
__device__ float g_nX  [MR*DD];
__device__ float g_qkv [(size_t)MR*QKVN];
__device__ float g_ctx [MR*DD];
__device__ float g_X1  [MR*DD];
__device__ float g_h   [(size_t)MR*FF];
__device__ float g_WqkvT[(size_t)QKVN*DD];
__device__ float g_WoT [DD*DD];
__device__ float g_W1T [(size_t)DD*FF];
__device__ float g_W2T [(size_t)DD*FF];

// ---------------- small helpers ---------------------------------------------
__device__ __forceinline__ uint32_t smem_u32(const void* p) {
    uint32_t a;
    asm("{ .reg .u64 t; cvta.to.shared.u64 t, %1; cvt.u32.u64 %0, t; }"
        : "=r"(a) : "l"(p));
    return a;
}
__device__ __forceinline__ float rna_tf32(float x) {
    uint32_t u;
    asm("cvt.rna.tf32.f32 %0, %1;" : "=r"(u) : "f"(x));
    return __uint_as_float(u);
}
__device__ __forceinline__ void cp16(uint32_t s, const void* g) {
    asm volatile("cp.async.cg.shared.global [%0], [%1], 16;" :: "r"(s), "l"(g));
}
__device__ __forceinline__ void mma_tf32(float* c, const uint32_t* a,
                                         const uint32_t* b) {
    asm volatile(
        "mma.sync.aligned.m16n8k8.row.col.f32.tf32.tf32.f32 "
        "{%0,%1,%2,%3}, {%4,%5,%6,%7}, {%8,%9}, {%0,%1,%2,%3};"
        : "+f"(c[0]), "+f"(c[1]), "+f"(c[2]), "+f"(c[3])
        : "r"(a[0]), "r"(a[1]), "r"(a[2]), "r"(a[3]),
          "r"(b[0]), "r"(b[1]));
}

// ---------------- weight transpose with tf32 round-to-nearest ---------------
__global__ __launch_bounds__(256)
void transpose_rna_kernel(const float* __restrict__ in, float* __restrict__ out,
                          int R, int C)
{
    __shared__ float t[32][33];
    const int bx = blockIdx.x * 32, by = blockIdx.y * 32;
    const int tx = threadIdx.x & 31, ty = threadIdx.x >> 5;  // 32 x 8
    #pragma unroll
    for (int i = 0; i < 32; i += 8)
        t[ty + i][tx] = in[(size_t)(by + ty + i) * C + bx + tx];
    __syncthreads();
    #pragma unroll
    for (int i = 0; i < 32; i += 8)
        out[(size_t)(bx + ty + i) * R + by + tx] = rna_tf32(t[tx][ty + i]);
}

// ---------------- LayerNorm (rna-rounded output) -----------------------------
__global__ __launch_bounds__(256)
void ln_kernel(const float* __restrict__ X, const float* __restrict__ g,
               const float* __restrict__ b, float* __restrict__ Y)
{
    const int row = blockIdx.x;
    const int tid = threadIdx.x;
    const float4 x = ((const float4*)(X + (size_t)row * DD))[tid];

    float s  = x.x + x.y + x.z + x.w;
    float ss = x.x*x.x + x.y*x.y + x.z*x.z + x.w*x.w;
    #pragma unroll
    for (int o = 16; o; o >>= 1) {
        s  += __shfl_xor_sync(0xffffffffu, s,  o);
        ss += __shfl_xor_sync(0xffffffffu, ss, o);
    }
    __shared__ float sw[8], sw2[8];
    const int w = tid >> 5, ln = tid & 31;
    if (ln == 0) { sw[w] = s; sw2[w] = ss; }
    __syncthreads();
    float tot = 0.f, tot2 = 0.f;
    #pragma unroll
    for (int i = 0; i < 8; i++) { tot += sw[i]; tot2 += sw2[i]; }

    const float mean = tot * (1.0f / DD);
    const float var  = tot2 * (1.0f / DD) - mean * mean;
    const float rstd = rsqrtf(var + 1e-5f);

    const float4 gv = ((const float4*)g)[tid];
    const float4 bv = ((const float4*)b)[tid];
    float4 y;
    y.x = rna_tf32((x.x - mean) * rstd * gv.x + bv.x);
    y.y = rna_tf32((x.y - mean) * rstd * gv.y + bv.y);
    y.z = rna_tf32((x.z - mean) * rstd * gv.z + bv.z);
    y.w = rna_tf32((x.w - mean) * rstd * gv.w + bv.w);
    ((float4*)(Y + (size_t)row * DD))[tid] = y;
}

// ---------------- tf32 mma.sync GEMM (templated m-tile) ----------------------
// C[M,N] = A[M,K] @ Bt[N,K]^T.  mode: 1=+bias, 2=+resid, 4=relu, 8=rna out
// MFRAG=2: CTA 128x128, warp 32x64, occ 2.  MFRAG=4: CTA 256x128, warp 64x64.
#define KSTR 36

template<int MFRAG>
__global__ void __launch_bounds__(256, (MFRAG == 2) ? 2 : 1)
tc_gemm(const float* __restrict__ A, const float* __restrict__ Bt,
        float* __restrict__ C, int M, int N, int K,
        const float* __restrict__ bias, const float* __restrict__ resid,
        int mode)
{
    constexpr int MT     = 64 * MFRAG;          // 128 or 256
    constexpr int TILEA  = MT * KSTR;
    constexpr int TILEB  = 128 * KSTR;
    constexpr int STG    = TILEA + TILEB;
    constexpr int ALOADS = MT / 32;             // float4 loads per thread for A

    extern __shared__ float smf[];
    const uint32_t sb = smem_u32(smf);

    const int tid  = threadIdx.x;
    const int wid  = tid >> 5, lane = tid & 31;
    const int tq   = lane >> 2, tr = lane & 3;
    const int wm   = (wid & 3) * (MT / 4);
    const int wn   = (wid >> 2) * 64;
    const int m0   = blockIdx.y * MT;
    const int n0   = blockIdx.x * 128;

    const int nk = K / 32;

    float acc[MFRAG][8][4];
    #pragma unroll
    for (int mt = 0; mt < MFRAG; mt++)
        #pragma unroll
        for (int nt = 0; nt < 8; nt++)
            #pragma unroll
            for (int i = 0; i < 4; i++) acc[mt][nt][i] = 0.f;

    {
        const uint32_t sA = sb, sB = sb + TILEA * 4;
        #pragma unroll
        for (int l = 0; l < ALOADS; l++) {
            const int idx = tid + l * 256;
            const int r = idx >> 3, c = idx & 7;
            cp16(sA + (uint32_t)(r * KSTR + c * 4) * 4,
                 A + (size_t)(m0 + r) * K + c * 4);
        }
        #pragma unroll
        for (int l = 0; l < 4; l++) {
            const int idx = tid + l * 256;
            const int r = idx >> 3, c = idx & 7;
            cp16(sB + (uint32_t)(r * KSTR + c * 4) * 4,
                 Bt + (size_t)(n0 + r) * K + c * 4);
        }
        asm volatile("cp.async.commit_group;" ::: "memory");
    }

    for (int kt = 0; kt < nk; kt++) {
        if (kt + 1 < nk) {
            const int s = (kt + 1) & 1;
            const uint32_t sA = sb + (uint32_t)s * STG * 4;
            const uint32_t sB = sA + TILEA * 4;
            const int kof = (kt + 1) * 32;
            #pragma unroll
            for (int l = 0; l < ALOADS; l++) {
                const int idx = tid + l * 256;
                const int r = idx >> 3, c = idx & 7;
                cp16(sA + (uint32_t)(r * KSTR + c * 4) * 4,
                     A + (size_t)(m0 + r) * K + kof + c * 4);
            }
            #pragma unroll
            for (int l = 0; l < 4; l++) {
                const int idx = tid + l * 256;
                const int r = idx >> 3, c = idx & 7;
                cp16(sB + (uint32_t)(r * KSTR + c * 4) * 4,
                     Bt + (size_t)(n0 + r) * K + kof + c * 4);
            }
            asm volatile("cp.async.commit_group;" ::: "memory");
            asm volatile("cp.async.wait_group 1;" ::: "memory");
        } else {
            asm volatile("cp.async.wait_group 0;" ::: "memory");
        }
        __syncthreads();

        const uint32_t* Asu = (const uint32_t*)(smf + (size_t)(kt & 1) * STG);
        const uint32_t* Bsu = Asu + TILEA;

        #pragma unroll
        for (int ks = 0; ks < 4; ks++) {
            const int kc = ks * 8 + tr;
            uint32_t a[MFRAG][4], b[8][2];
            #pragma unroll
            for (int mt = 0; mt < MFRAG; mt++) {
                const int row = wm + mt * 16 + tq;
                a[mt][0] = Asu[row * KSTR + kc];
                a[mt][1] = Asu[(row + 8) * KSTR + kc];
                a[mt][2] = Asu[row * KSTR + kc + 4];
                a[mt][3] = Asu[(row + 8) * KSTR + kc + 4];
            }
            #pragma unroll
            for (int nt = 0; nt < 8; nt++) {
                const int col = wn + nt * 8 + tq;
                b[nt][0] = Bsu[col * KSTR + kc];
                b[nt][1] = Bsu[col * KSTR + kc + 4];
            }
            #pragma unroll
            for (int mt = 0; mt < MFRAG; mt++)
                #pragma unroll
                for (int nt = 0; nt < 8; nt++)
                    mma_tf32(acc[mt][nt], a[mt], b[nt]);
        }
        __syncthreads();
    }

    #pragma unroll
    for (int mt = 0; mt < MFRAG; mt++) {
        const int r0 = m0 + wm + mt * 16 + tq;
        #pragma unroll
        for (int half = 0; half < 2; half++) {
            const int m = r0 + half * 8;
            #pragma unroll
            for (int nt = 0; nt < 8; nt++) {
                const int n = n0 + wn + nt * 8 + tr * 2;
                float vx = acc[mt][nt][half * 2 + 0];
                float vy = acc[mt][nt][half * 2 + 1];
                if (mode & 1) {
                    const float2 bb = *(const float2*)(bias + n);
                    vx += bb.x; vy += bb.y;
                }
                if (mode & 2) {
                    const float2 rr = *(const float2*)(resid + (size_t)m * N + n);
                    vx += rr.x; vy += rr.y;
                }
                if (mode & 4) { vx = fmaxf(vx, 0.f); vy = fmaxf(vy, 0.f); }
                if (mode & 8) { vx = rna_tf32(vx); vy = rna_tf32(vy); }
                float2 o; o.x = vx; o.y = vy;
                *(float2*)(C + (size_t)m * N + n) = o;
            }
        }
    }
}

#define TC_SMEM2 (2 * (128 * KSTR + 128 * KSTR) * 4)   // 73728
#define TC_SMEM4 (2 * (256 * KSTR + 128 * KSTR) * 4)   // 110592

// ---------------- Flash attention on tensor cores (tf32 mma) ------------------
#define ASQ 68
#define ASV 72
#define ATT_SMEM ((128*ASQ + 64*ASQ + 64*ASV + 128*ASQ) * 4)   // 105472 B

__global__ __launch_bounds__(256, 2)
void attn_mma_kernel(const float* __restrict__ QKVg, float* __restrict__ Og,
                     int ldi)
{
    extern __shared__ float sm[];
    float* Qs = sm;                       // [128][68]
    float* Ks = sm + 128 * ASQ;           // [64][68]
    float* Vs = Ks + 64 * ASQ;            // [64][72]
    float* Ps = Vs + 64 * ASV;            // [128][68]

    const int tid  = threadIdx.x;
    const int wid  = tid >> 5, lane = tid & 31;
    const int tq   = lane >> 2, tr = lane & 3;
    const int wq0  = wid * 16;
    const int bh   = blockIdx.y;
    const int b    = bh >> 4, h = bh & 15;
    const size_t base_i = (size_t)b * SS * ldi + (size_t)h * DK;
    const size_t base_o = (size_t)b * SS * DD + (size_t)h * DK;
    const int q0   = blockIdx.x * 128;

    const float* Qg = QKVg + base_i;
    const float* Kg = QKVg + base_i + DD;
    const float* Vg = QKVg + base_i + 2 * DD;

    // load Q tile: 128x64, scaled 1/8, rna to tf32
    #pragma unroll
    for (int l = 0; l < 8; l++) {
        const int idx = tid + l * 256;
        const int r = idx >> 4, c = (idx & 15) << 2;
        float4 qv = *(const float4*)(Qg + (size_t)(q0 + r) * ldi + c);
        float4 w;
        w.x = rna_tf32(qv.x * 0.125f); w.y = rna_tf32(qv.y * 0.125f);
        w.z = rna_tf32(qv.z * 0.125f); w.w = rna_tf32(qv.w * 0.125f);
        *(float4*)(Qs + r * ASQ + c) = w;
    }

    float m_[2], l_[2], o[8][4];
    m_[0] = m_[1] = -CUDART_INF_F;
    l_[0] = l_[1] = 0.f;
    #pragma unroll
    for (int nt = 0; nt < 8; nt++)
        #pragma unroll
        for (int i = 0; i < 4; i++) o[nt][i] = 0.f;

    const uint32_t* Qu = (const uint32_t*)Qs;
    const uint32_t* Ku = (const uint32_t*)Ks;
    const uint32_t* Vu = (const uint32_t*)Vs;
    const uint32_t* Pu = (const uint32_t*)Ps;

    for (int kt = 0; kt < SS / 64; kt++) {
        __syncthreads();
        const int kb = kt * 64;
        #pragma unroll
        for (int l = 0; l < 4; l++) {
            const int idx = tid + l * 256;
            const int r = idx >> 4, c = (idx & 15) << 2;
            float4 kv = *(const float4*)(Kg + (size_t)(kb + r) * ldi + c);
            float4 wk;
            wk.x = rna_tf32(kv.x); wk.y = rna_tf32(kv.y);
            wk.z = rna_tf32(kv.z); wk.w = rna_tf32(kv.w);
            *(float4*)(Ks + r * ASQ + c) = wk;
            float4 vv = *(const float4*)(Vg + (size_t)(kb + r) * ldi + c);
            float4 wv;
            wv.x = rna_tf32(vv.x); wv.y = rna_tf32(vv.y);
            wv.z = rna_tf32(vv.z); wv.w = rna_tf32(vv.w);
            *(float4*)(Vs + r * ASV + c) = wv;
        }
        __syncthreads();

        float s[8][4];
        #pragma unroll
        for (int nt = 0; nt < 8; nt++)
            #pragma unroll
            for (int i = 0; i < 4; i++) s[nt][i] = 0.f;

        #pragma unroll
        for (int ks = 0; ks < 8; ks++) {
            const int kc = ks * 8 + tr;
            uint32_t a[4];
            a[0] = Qu[(wq0 + tq) * ASQ + kc];
            a[1] = Qu[(wq0 + tq + 8) * ASQ + kc];
            a[2] = Qu[(wq0 + tq) * ASQ + kc + 4];
            a[3] = Qu[(wq0 + tq + 8) * ASQ + kc + 4];
            #pragma unroll
            for (int nt = 0; nt < 8; nt++) {
                uint32_t bb[2];
                bb[0] = Ku[(nt * 8 + tq) * ASQ + kc];
                bb[1] = Ku[(nt * 8 + tq) * ASQ + kc + 4];
                mma_tf32(s[nt], a, bb);
            }
        }

        #pragma unroll
        for (int half = 0; half < 2; half++) {
            float mx = -CUDART_INF_F;
            #pragma unroll
            for (int nt = 0; nt < 8; nt++)
                mx = fmaxf(mx, fmaxf(s[nt][half * 2], s[nt][half * 2 + 1]));
            mx = fmaxf(mx, __shfl_xor_sync(0xffffffffu, mx, 1));
            mx = fmaxf(mx, __shfl_xor_sync(0xffffffffu, mx, 2));
            const float mn   = fmaxf(m_[half], mx);
            const float corr = __expf(m_[half] - mn);
            m_[half] = mn;
            float sum = 0.f;
            #pragma unroll
            for (int nt = 0; nt < 8; nt++) {
                float p0 = __expf(s[nt][half * 2]     - mn);
                float p1 = __expf(s[nt][half * 2 + 1] - mn);
                s[nt][half * 2]     = p0;
                s[nt][half * 2 + 1] = p1;
                sum += p0 + p1;
            }
            sum += __shfl_xor_sync(0xffffffffu, sum, 1);
            sum += __shfl_xor_sync(0xffffffffu, sum, 2);
            l_[half] = l_[half] * corr + sum;
            #pragma unroll
            for (int nt = 0; nt < 8; nt++) {
                o[nt][half * 2]     *= corr;
                o[nt][half * 2 + 1] *= corr;
            }
        }

        #pragma unroll
        for (int nt = 0; nt < 8; nt++) {
            const int col = nt * 8 + tr * 2;
            float2 p0, p1;
            p0.x = rna_tf32(s[nt][0]); p0.y = rna_tf32(s[nt][1]);
            p1.x = rna_tf32(s[nt][2]); p1.y = rna_tf32(s[nt][3]);
            *(float2*)(Ps + (wq0 + tq) * ASQ + col)     = p0;
            *(float2*)(Ps + (wq0 + tq + 8) * ASQ + col) = p1;
        }
        __syncwarp();

        #pragma unroll
        for (int ks = 0; ks < 8; ks++) {
            const int kc = ks * 8 + tr;
            uint32_t a[4];
            a[0] = Pu[(wq0 + tq) * ASQ + kc];
            a[1] = Pu[(wq0 + tq + 8) * ASQ + kc];
            a[2] = Pu[(wq0 + tq) * ASQ + kc + 4];
            a[3] = Pu[(wq0 + tq + 8) * ASQ + kc + 4];
            #pragma unroll
            for (int nt = 0; nt < 8; nt++) {
                uint32_t bb[2];
                bb[0] = Vu[kc * ASV + nt * 8 + tq];
                bb[1] = Vu[(kc + 4) * ASV + nt * 8 + tq];
                mma_tf32(o[nt], a, bb);
            }
        }
    }

    const float inv0 = 1.0f / l_[0];
    const float inv1 = 1.0f / l_[1];
    #pragma unroll
    for (int nt = 0; nt < 8; nt++) {
        const int col = nt * 8 + tr * 2;
        float2 o0, o1;
        o0.x = rna_tf32(o[nt][0] * inv0); o0.y = rna_tf32(o[nt][1] * inv0);
        o1.x = rna_tf32(o[nt][2] * inv1); o1.y = rna_tf32(o[nt][3] * inv1);
        *(float2*)(Og + base_o + (size_t)(q0 + wq0 + tq) * DD + col)     = o0;
        *(float2*)(Og + base_o + (size_t)(q0 + wq0 + tq + 8) * DD + col) = o1;
    }
}

// ---------------- launch -----------------------------------------------------
extern "C" void kernel_launch(void* const* d_in, const int* in_sizes, int n_in,
                              void* d_out, int out_size)
{
    const float* X   = (const float*)d_in[0];
    const float* Wq  = (const float*)d_in[1];
    const float* Wk  = (const float*)d_in[2];
    const float* Wv  = (const float*)d_in[3];
    const float* Wo  = (const float*)d_in[4];
    const float* W1  = (const float*)d_in[5];
    const float* b1  = (const float*)d_in[6];
    const float* W2  = (const float*)d_in[7];
    const float* b2  = (const float*)d_in[8];
    const float* g1  = (const float*)d_in[9];
    const float* be1 = (const float*)d_in[10];
    const float* g2  = (const float*)d_in[11];
    const float* be2 = (const float*)d_in[12];
    float* out = (float*)d_out;

    float *nX, *qkv, *ctx, *X1, *hbuf;
    float *WqkvT, *WoT, *W1T, *W2T;
    cudaGetSymbolAddress((void**)&nX,    g_nX);
    cudaGetSymbolAddress((void**)&qkv,   g_qkv);
    cudaGetSymbolAddress((void**)&ctx,   g_ctx);
    cudaGetSymbolAddress((void**)&X1,    g_X1);
    cudaGetSymbolAddress((void**)&hbuf,  g_h);
    cudaGetSymbolAddress((void**)&WqkvT, g_WqkvT);
    cudaGetSymbolAddress((void**)&WoT,   g_WoT);
    cudaGetSymbolAddress((void**)&W1T,   g_W1T);
    cudaGetSymbolAddress((void**)&W2T,   g_W2T);

    cudaFuncSetAttribute(tc_gemm<2>, cudaFuncAttributeMaxDynamicSharedMemorySize,
                         TC_SMEM2);
    cudaFuncSetAttribute(tc_gemm<4>, cudaFuncAttributeMaxDynamicSharedMemorySize,
                         TC_SMEM4);
    cudaFuncSetAttribute(attn_mma_kernel,
                         cudaFuncAttributeMaxDynamicSharedMemorySize, ATT_SMEM);

    dim3 thr(256);

    // launches 1-5 (so that launch #6 = big tc_gemm for ncu -s 5 -c 1)
    transpose_rna_kernel<<<dim3(DD/32, DD/32), thr>>>(Wq, WqkvT, DD, DD);
    transpose_rna_kernel<<<dim3(DD/32, DD/32), thr>>>(Wk, WqkvT + DD*DD, DD, DD);
    transpose_rna_kernel<<<dim3(DD/32, DD/32), thr>>>(Wv, WqkvT + 2*DD*DD, DD, DD);
    ln_kernel<<<MR, thr>>>(X, g1, be1, nX);
    transpose_rna_kernel<<<dim3(DD/32, DD/32), thr>>>(Wo, WoT, DD, DD);

    // launch 6: fused QKV projection (captured by ncu)
    tc_gemm<4><<<dim3(QKVN/128, MR/256), thr, TC_SMEM4>>>(
        nX, WqkvT, qkv, MR, QKVN, DD, nullptr, nullptr, 0);

    // attention (tensor-core flash), reads fused qkv (ldi=3072)
    attn_mma_kernel<<<dim3(SS/128, BB*HH), thr, ATT_SMEM>>>(qkv, ctx, QKVN);

    // output projection + residual
    tc_gemm<2><<<dim3(DD/128, MR/128), thr, TC_SMEM2>>>(
        ctx, WoT, X1, MR, DD, DD, nullptr, X, 2);

    // LN2
    ln_kernel<<<MR, thr>>>(X1, g2, be2, nX);

    // FFN weight transposes
    transpose_rna_kernel<<<dim3(FF/32, DD/32), thr>>>(W1, W1T, DD, FF);
    transpose_rna_kernel<<<dim3(DD/32, FF/32), thr>>>(W2, W2T, FF, DD);

    // FFN up: h = rna(relu(nX @ W1 + b1))
    tc_gemm<4><<<dim3(FF/128, MR/256), thr, TC_SMEM4>>>(
        nX, W1T, hbuf, MR, FF, DD, b1, nullptr, 1 | 4 | 8);

    // FFN down + residual: out = X1 + h @ W2 + b2
    tc_gemm<2><<<dim3(DD/128, MR/128), thr, TC_SMEM2>>>(
        hbuf, W2T, out, MR, DD, FF, b2, X1, 1 | 2);
}

// round 6
// speedup vs baseline: 1.0953x; 1.0953x over previous
#include <cuda_runtime.h>
#include <cuda_bf16.h>
#include <math_constants.h>
#include <cstdint>

// Problem constants
#define BB 2
#define SS 2048
#define DD 1024
#define HH 16
#define DK 64
#define FF 4096
#define MR (BB*SS)          // 4096 rows
#define QKVN 3072

// ---------------- scratch (static device globals: alloc-free rule) ----------
__device__ float g_nX  [MR*DD];
__device__ float g_qkv [(size_t)MR*QKVN];
__device__ float g_ctx [MR*DD];
__device__ float g_X1  [MR*DD];
__device__ float g_h   [(size_t)MR*FF];
__device__ float g_WqkvT[(size_t)QKVN*DD];
__device__ float g_WoT [DD*DD];
__device__ float g_W1T [(size_t)DD*FF];
__device__ float g_W2T [(size_t)DD*FF];

// ---------------- small helpers ---------------------------------------------
__device__ __forceinline__ uint32_t smem_u32(const void* p) {
    uint32_t a;
    asm("{ .reg .u64 t; cvta.to.shared.u64 t, %1; cvt.u32.u64 %0, t; }"
        : "=r"(a) : "l"(p));
    return a;
}
__device__ __forceinline__ float rna_tf32(float x) {
    uint32_t u;
    asm("cvt.rna.tf32.f32 %0, %1;" : "=r"(u) : "f"(x));
    return __uint_as_float(u);
}
__device__ __forceinline__ void cp16(uint32_t s, const void* g) {
    asm volatile("cp.async.cg.shared.global [%0], [%1], 16;" :: "r"(s), "l"(g));
}
__device__ __forceinline__ void ldsm4(uint32_t* r, uint32_t addr) {
    asm volatile(
        "ldmatrix.sync.aligned.m8n8.x4.shared.b16 {%0,%1,%2,%3}, [%4];"
        : "=r"(r[0]), "=r"(r[1]), "=r"(r[2]), "=r"(r[3]) : "r"(addr));
}
__device__ __forceinline__ void mma_tf32(float* c, const uint32_t* a,
                                         const uint32_t* b) {
    asm volatile(
        "mma.sync.aligned.m16n8k8.row.col.f32.tf32.tf32.f32 "
        "{%0,%1,%2,%3}, {%4,%5,%6,%7}, {%8,%9}, {%0,%1,%2,%3};"
        : "+f"(c[0]), "+f"(c[1]), "+f"(c[2]), "+f"(c[3])
        : "r"(a[0]), "r"(a[1]), "r"(a[2]), "r"(a[3]),
          "r"(b[0]), "r"(b[1]));
}

// ---------------- weight transpose with tf32 round-to-nearest ---------------
__global__ __launch_bounds__(256)
void transpose_rna_kernel(const float* __restrict__ in, float* __restrict__ out,
                          int R, int C)
{
    __shared__ float t[32][33];
    const int bx = blockIdx.x * 32, by = blockIdx.y * 32;
    const int tx = threadIdx.x & 31, ty = threadIdx.x >> 5;  // 32 x 8
    #pragma unroll
    for (int i = 0; i < 32; i += 8)
        t[ty + i][tx] = in[(size_t)(by + ty + i) * C + bx + tx];
    __syncthreads();
    #pragma unroll
    for (int i = 0; i < 32; i += 8)
        out[(size_t)(bx + ty + i) * R + by + tx] = rna_tf32(t[tx][ty + i]);
}

// ---------------- LayerNorm (rna-rounded output) -----------------------------
__global__ __launch_bounds__(256)
void ln_kernel(const float* __restrict__ X, const float* __restrict__ g,
               const float* __restrict__ b, float* __restrict__ Y)
{
    const int row = blockIdx.x;
    const int tid = threadIdx.x;
    const float4 x = ((const float4*)(X + (size_t)row * DD))[tid];

    float s  = x.x + x.y + x.z + x.w;
    float ss = x.x*x.x + x.y*x.y + x.z*x.z + x.w*x.w;
    #pragma unroll
    for (int o = 16; o; o >>= 1) {
        s  += __shfl_xor_sync(0xffffffffu, s,  o);
        ss += __shfl_xor_sync(0xffffffffu, ss, o);
    }
    __shared__ float sw[8], sw2[8];
    const int w = tid >> 5, ln = tid & 31;
    if (ln == 0) { sw[w] = s; sw2[w] = ss; }
    __syncthreads();
    float tot = 0.f, tot2 = 0.f;
    #pragma unroll
    for (int i = 0; i < 8; i++) { tot += sw[i]; tot2 += sw2[i]; }

    const float mean = tot * (1.0f / DD);
    const float var  = tot2 * (1.0f / DD) - mean * mean;
    const float rstd = rsqrtf(var + 1e-5f);

    const float4 gv = ((const float4*)g)[tid];
    const float4 bv = ((const float4*)b)[tid];
    float4 y;
    y.x = rna_tf32((x.x - mean) * rstd * gv.x + bv.x);
    y.y = rna_tf32((x.y - mean) * rstd * gv.y + bv.y);
    y.z = rna_tf32((x.z - mean) * rstd * gv.z + bv.z);
    y.w = rna_tf32((x.w - mean) * rstd * gv.w + bv.w);
    ((float4*)(Y + (size_t)row * DD))[tid] = y;
}

// ---------------- tf32 mma.sync GEMM with ldmatrix operand loads -------------
// C[M,N] = A[M,K] @ Bt[N,K]^T.  mode: 1=+bias, 2=+resid, 4=relu, 8=rna out
// CTA 128x128, warp 32x64, 2-stage cp.async, occupancy 2.
#define KSTR 36
#define TILEA (128 * KSTR)
#define STG   (2 * TILEA)                      // A tile + B tile (floats)
#define TC_SMEM (2 * STG * 4)                  // 73728 bytes

__global__ void __launch_bounds__(256, 2)
tc_gemm(const float* __restrict__ A, const float* __restrict__ Bt,
        float* __restrict__ C, int M, int N, int K,
        const float* __restrict__ bias, const float* __restrict__ resid,
        int mode)
{
    extern __shared__ float smf[];
    const uint32_t sb = smem_u32(smf);

    const int tid  = threadIdx.x;
    const int wid  = tid >> 5, lane = tid & 31;
    const int tq   = lane >> 2, tr = lane & 3;
    const int wm   = (wid & 3) * 32;
    const int wn   = (wid >> 2) * 64;
    const int m0   = blockIdx.y * 128;
    const int n0   = blockIdx.x * 128;

    const int nk = K / 32;

    // ldmatrix lane addresses (byte offsets inside stage 0)
    // A frag (mt): rows wm+mt*16+(lane&15), col halves by lane>=16
    uint32_t a_addr[2];
    #pragma unroll
    for (int mt = 0; mt < 2; mt++) {
        const int row = wm + mt * 16 + (lane & 15);
        const int col = (lane >> 4) << 2;              // 0 or 4
        a_addr[mt] = sb + (uint32_t)(row * KSTR + col) * 4u;
    }
    // B frag (j covers nt=2j,2j+1): rows wn+j*16+((lane>>4)<<3)+(lane&7),
    // col half by bit3
    uint32_t b_addr[4];
    #pragma unroll
    for (int j = 0; j < 4; j++) {
        const int row = wn + j * 16 + ((lane >> 4) << 3) + (lane & 7);
        const int col = ((lane >> 3) & 1) << 2;        // 0 or 4
        b_addr[j] = sb + (uint32_t)(TILEA + row * KSTR + col) * 4u;
    }

    float acc[2][8][4];
    #pragma unroll
    for (int mt = 0; mt < 2; mt++)
        #pragma unroll
        for (int nt = 0; nt < 8; nt++)
            #pragma unroll
            for (int i = 0; i < 4; i++) acc[mt][nt][i] = 0.f;

    {
        const uint32_t sA = sb, sB = sb + TILEA * 4;
        #pragma unroll
        for (int l = 0; l < 4; l++) {
            const int idx = tid + l * 256;
            const int r = idx >> 3, c = idx & 7;
            cp16(sA + (uint32_t)(r * KSTR + c * 4) * 4,
                 A + (size_t)(m0 + r) * K + c * 4);
            cp16(sB + (uint32_t)(r * KSTR + c * 4) * 4,
                 Bt + (size_t)(n0 + r) * K + c * 4);
        }
        asm volatile("cp.async.commit_group;" ::: "memory");
    }

    for (int kt = 0; kt < nk; kt++) {
        if (kt + 1 < nk) {
            const int s = (kt + 1) & 1;
            const uint32_t sA = sb + (uint32_t)s * STG * 4;
            const uint32_t sB = sA + TILEA * 4;
            const int kof = (kt + 1) * 32;
            #pragma unroll
            for (int l = 0; l < 4; l++) {
                const int idx = tid + l * 256;
                const int r = idx >> 3, c = idx & 7;
                cp16(sA + (uint32_t)(r * KSTR + c * 4) * 4,
                     A + (size_t)(m0 + r) * K + kof + c * 4);
                cp16(sB + (uint32_t)(r * KSTR + c * 4) * 4,
                     Bt + (size_t)(n0 + r) * K + kof + c * 4);
            }
            asm volatile("cp.async.commit_group;" ::: "memory");
            asm volatile("cp.async.wait_group 1;" ::: "memory");
        } else {
            asm volatile("cp.async.wait_group 0;" ::: "memory");
        }
        __syncthreads();

        const uint32_t stg_off = (uint32_t)(kt & 1) * STG * 4u;

        #pragma unroll
        for (int ks = 0; ks < 4; ks++) {
            const uint32_t koff = stg_off + (uint32_t)ks * 32u;   // 8 floats
            uint32_t a[2][4], bfr[4][4];
            #pragma unroll
            for (int mt = 0; mt < 2; mt++)
                ldsm4(a[mt], a_addr[mt] + koff);
            #pragma unroll
            for (int j = 0; j < 4; j++)
                ldsm4(bfr[j], b_addr[j] + koff);
            #pragma unroll
            for (int mt = 0; mt < 2; mt++)
                #pragma unroll
                for (int j = 0; j < 4; j++) {
                    mma_tf32(acc[mt][2*j],   a[mt], &bfr[j][0]);
                    mma_tf32(acc[mt][2*j+1], a[mt], &bfr[j][2]);
                }
        }
        __syncthreads();
    }

    #pragma unroll
    for (int mt = 0; mt < 2; mt++) {
        const int r0 = m0 + wm + mt * 16 + tq;
        #pragma unroll
        for (int half = 0; half < 2; half++) {
            const int m = r0 + half * 8;
            #pragma unroll
            for (int nt = 0; nt < 8; nt++) {
                const int n = n0 + wn + nt * 8 + tr * 2;
                float vx = acc[mt][nt][half * 2 + 0];
                float vy = acc[mt][nt][half * 2 + 1];
                if (mode & 1) {
                    const float2 bb = *(const float2*)(bias + n);
                    vx += bb.x; vy += bb.y;
                }
                if (mode & 2) {
                    const float2 rr = *(const float2*)(resid + (size_t)m * N + n);
                    vx += rr.x; vy += rr.y;
                }
                if (mode & 4) { vx = fmaxf(vx, 0.f); vy = fmaxf(vy, 0.f); }
                if (mode & 8) { vx = rna_tf32(vx); vy = rna_tf32(vy); }
                float2 o; o.x = vx; o.y = vy;
                *(float2*)(C + (size_t)m * N + n) = o;
            }
        }
    }
}

// ---------------- Flash attention on tensor cores (tf32 mma) ------------------
#define ASQ 68
#define ASV 72
#define ATT_SMEM ((128*ASQ + 64*ASQ + 64*ASV + 128*ASQ) * 4)   // 105472 B

__global__ __launch_bounds__(256, 2)
void attn_mma_kernel(const float* __restrict__ QKVg, float* __restrict__ Og,
                     int ldi)
{
    extern __shared__ float sm[];
    float* Qs = sm;                       // [128][68]
    float* Ks = sm + 128 * ASQ;           // [64][68]
    float* Vs = Ks + 64 * ASQ;            // [64][72]
    float* Ps = Vs + 64 * ASV;            // [128][68]

    const int tid  = threadIdx.x;
    const int wid  = tid >> 5, lane = tid & 31;
    const int tq   = lane >> 2, tr = lane & 3;
    const int wq0  = wid * 16;
    const int bh   = blockIdx.y;
    const int b    = bh >> 4, h = bh & 15;
    const size_t base_i = (size_t)b * SS * ldi + (size_t)h * DK;
    const size_t base_o = (size_t)b * SS * DD + (size_t)h * DK;
    const int q0   = blockIdx.x * 128;

    const float* Qg = QKVg + base_i;
    const float* Kg = QKVg + base_i + DD;
    const float* Vg = QKVg + base_i + 2 * DD;

    #pragma unroll
    for (int l = 0; l < 8; l++) {
        const int idx = tid + l * 256;
        const int r = idx >> 4, c = (idx & 15) << 2;
        float4 qv = *(const float4*)(Qg + (size_t)(q0 + r) * ldi + c);
        float4 w;
        w.x = rna_tf32(qv.x * 0.125f); w.y = rna_tf32(qv.y * 0.125f);
        w.z = rna_tf32(qv.z * 0.125f); w.w = rna_tf32(qv.w * 0.125f);
        *(float4*)(Qs + r * ASQ + c) = w;
    }

    float m_[2], l_[2], o[8][4];
    m_[0] = m_[1] = -CUDART_INF_F;
    l_[0] = l_[1] = 0.f;
    #pragma unroll
    for (int nt = 0; nt < 8; nt++)
        #pragma unroll
        for (int i = 0; i < 4; i++) o[nt][i] = 0.f;

    const uint32_t* Qu = (const uint32_t*)Qs;
    const uint32_t* Ku = (const uint32_t*)Ks;
    const uint32_t* Vu = (const uint32_t*)Vs;
    const uint32_t* Pu = (const uint32_t*)Ps;

    for (int kt = 0; kt < SS / 64; kt++) {
        __syncthreads();
        const int kb = kt * 64;
        #pragma unroll
        for (int l = 0; l < 4; l++) {
            const int idx = tid + l * 256;
            const int r = idx >> 4, c = (idx & 15) << 2;
            float4 kv = *(const float4*)(Kg + (size_t)(kb + r) * ldi + c);
            float4 wk;
            wk.x = rna_tf32(kv.x); wk.y = rna_tf32(kv.y);
            wk.z = rna_tf32(kv.z); wk.w = rna_tf32(kv.w);
            *(float4*)(Ks + r * ASQ + c) = wk;
            float4 vv = *(const float4*)(Vg + (size_t)(kb + r) * ldi + c);
            float4 wv;
            wv.x = rna_tf32(vv.x); wv.y = rna_tf32(vv.y);
            wv.z = rna_tf32(vv.z); wv.w = rna_tf32(vv.w);
            *(float4*)(Vs + r * ASV + c) = wv;
        }
        __syncthreads();

        float s[8][4];
        #pragma unroll
        for (int nt = 0; nt < 8; nt++)
            #pragma unroll
            for (int i = 0; i < 4; i++) s[nt][i] = 0.f;

        #pragma unroll
        for (int ks = 0; ks < 8; ks++) {
            const int kc = ks * 8 + tr;
            uint32_t a[4];
            a[0] = Qu[(wq0 + tq) * ASQ + kc];
            a[1] = Qu[(wq0 + tq + 8) * ASQ + kc];
            a[2] = Qu[(wq0 + tq) * ASQ + kc + 4];
            a[3] = Qu[(wq0 + tq + 8) * ASQ + kc + 4];
            #pragma unroll
            for (int nt = 0; nt < 8; nt++) {
                uint32_t bb[2];
                bb[0] = Ku[(nt * 8 + tq) * ASQ + kc];
                bb[1] = Ku[(nt * 8 + tq) * ASQ + kc + 4];
                mma_tf32(s[nt], a, bb);
            }
        }

        #pragma unroll
        for (int half = 0; half < 2; half++) {
            float mx = -CUDART_INF_F;
            #pragma unroll
            for (int nt = 0; nt < 8; nt++)
                mx = fmaxf(mx, fmaxf(s[nt][half * 2], s[nt][half * 2 + 1]));
            mx = fmaxf(mx, __shfl_xor_sync(0xffffffffu, mx, 1));
            mx = fmaxf(mx, __shfl_xor_sync(0xffffffffu, mx, 2));
            const float mn   = fmaxf(m_[half], mx);
            const float corr = __expf(m_[half] - mn);
            m_[half] = mn;
            float sum = 0.f;
            #pragma unroll
            for (int nt = 0; nt < 8; nt++) {
                float p0 = __expf(s[nt][half * 2]     - mn);
                float p1 = __expf(s[nt][half * 2 + 1] - mn);
                s[nt][half * 2]     = p0;
                s[nt][half * 2 + 1] = p1;
                sum += p0 + p1;
            }
            sum += __shfl_xor_sync(0xffffffffu, sum, 1);
            sum += __shfl_xor_sync(0xffffffffu, sum, 2);
            l_[half] = l_[half] * corr + sum;
            #pragma unroll
            for (int nt = 0; nt < 8; nt++) {
                o[nt][half * 2]     *= corr;
                o[nt][half * 2 + 1] *= corr;
            }
        }

        #pragma unroll
        for (int nt = 0; nt < 8; nt++) {
            const int col = nt * 8 + tr * 2;
            float2 p0, p1;
            p0.x = rna_tf32(s[nt][0]); p0.y = rna_tf32(s[nt][1]);
            p1.x = rna_tf32(s[nt][2]); p1.y = rna_tf32(s[nt][3]);
            *(float2*)(Ps + (wq0 + tq) * ASQ + col)     = p0;
            *(float2*)(Ps + (wq0 + tq + 8) * ASQ + col) = p1;
        }
        __syncwarp();

        #pragma unroll
        for (int ks = 0; ks < 8; ks++) {
            const int kc = ks * 8 + tr;
            uint32_t a[4];
            a[0] = Pu[(wq0 + tq) * ASQ + kc];
            a[1] = Pu[(wq0 + tq + 8) * ASQ + kc];
            a[2] = Pu[(wq0 + tq) * ASQ + kc + 4];
            a[3] = Pu[(wq0 + tq + 8) * ASQ + kc + 4];
            #pragma unroll
            for (int nt = 0; nt < 8; nt++) {
                uint32_t bb[2];
                bb[0] = Vu[kc * ASV + nt * 8 + tq];
                bb[1] = Vu[(kc + 4) * ASV + nt * 8 + tq];
                mma_tf32(o[nt], a, bb);
            }
        }
    }

    const float inv0 = 1.0f / l_[0];
    const float inv1 = 1.0f / l_[1];
    #pragma unroll
    for (int nt = 0; nt < 8; nt++) {
        const int col = nt * 8 + tr * 2;
        float2 o0, o1;
        o0.x = rna_tf32(o[nt][0] * inv0); o0.y = rna_tf32(o[nt][1] * inv0);
        o1.x = rna_tf32(o[nt][2] * inv1); o1.y = rna_tf32(o[nt][3] * inv1);
        *(float2*)(Og + base_o + (size_t)(q0 + wq0 + tq) * DD + col)     = o0;
        *(float2*)(Og + base_o + (size_t)(q0 + wq0 + tq + 8) * DD + col) = o1;
    }
}

// ---------------- launch -----------------------------------------------------
extern "C" void kernel_launch(void* const* d_in, const int* in_sizes, int n_in,
                              void* d_out, int out_size)
{
    const float* X   = (const float*)d_in[0];
    const float* Wq  = (const float*)d_in[1];
    const float* Wk  = (const float*)d_in[2];
    const float* Wv  = (const float*)d_in[3];
    const float* Wo  = (const float*)d_in[4];
    const float* W1  = (const float*)d_in[5];
    const float* b1  = (const float*)d_in[6];
    const float* W2  = (const float*)d_in[7];
    const float* b2  = (const float*)d_in[8];
    const float* g1  = (const float*)d_in[9];
    const float* be1 = (const float*)d_in[10];
    const float* g2  = (const float*)d_in[11];
    const float* be2 = (const float*)d_in[12];
    float* out = (float*)d_out;

    float *nX, *qkv, *ctx, *X1, *hbuf;
    float *WqkvT, *WoT, *W1T, *W2T;
    cudaGetSymbolAddress((void**)&nX,    g_nX);
    cudaGetSymbolAddress((void**)&qkv,   g_qkv);
    cudaGetSymbolAddress((void**)&ctx,   g_ctx);
    cudaGetSymbolAddress((void**)&X1,    g_X1);
    cudaGetSymbolAddress((void**)&hbuf,  g_h);
    cudaGetSymbolAddress((void**)&WqkvT, g_WqkvT);
    cudaGetSymbolAddress((void**)&WoT,   g_WoT);
    cudaGetSymbolAddress((void**)&W1T,   g_W1T);
    cudaGetSymbolAddress((void**)&W2T,   g_W2T);

    cudaFuncSetAttribute(tc_gemm, cudaFuncAttributeMaxDynamicSharedMemorySize,
                         TC_SMEM);
    cudaFuncSetAttribute(attn_mma_kernel,
                         cudaFuncAttributeMaxDynamicSharedMemorySize, ATT_SMEM);

    dim3 thr(256);

    // weight transposes (rna-rounded to tf32)
    transpose_rna_kernel<<<dim3(DD/32, DD/32), thr>>>(Wq, WqkvT, DD, DD);
    transpose_rna_kernel<<<dim3(DD/32, DD/32), thr>>>(Wk, WqkvT + DD*DD, DD, DD);
    transpose_rna_kernel<<<dim3(DD/32, DD/32), thr>>>(Wv, WqkvT + 2*DD*DD, DD, DD);
    transpose_rna_kernel<<<dim3(DD/32, DD/32), thr>>>(Wo, WoT, DD, DD);
    transpose_rna_kernel<<<dim3(FF/32, DD/32), thr>>>(W1, W1T, DD, FF);
    transpose_rna_kernel<<<dim3(DD/32, FF/32), thr>>>(W2, W2T, FF, DD);

    // LN1
    ln_kernel<<<MR, thr>>>(X, g1, be1, nX);

    // fused QKV projection
    tc_gemm<<<dim3(QKVN/128, MR/128), thr, TC_SMEM>>>(
        nX, WqkvT, qkv, MR, QKVN, DD, nullptr, nullptr, 0);

    // attention (tensor-core flash), reads fused qkv (ldi=3072)
    attn_mma_kernel<<<dim3(SS/128, BB*HH), thr, ATT_SMEM>>>(qkv, ctx, QKVN);

    // output projection + residual
    tc_gemm<<<dim3(DD/128, MR/128), thr, TC_SMEM>>>(
        ctx, WoT, X1, MR, DD, DD, nullptr, X, 2);

    // LN2
    ln_kernel<<<MR, thr>>>(X1, g2, be2, nX);

    // FFN up: h = rna(relu(nX @ W1 + b1))
    tc_gemm<<<dim3(FF/128, MR/128), thr, TC_SMEM>>>(
        nX, W1T, hbuf, MR, FF, DD, b1, nullptr, 1 | 4 | 8);

    // FFN down + residual: out = X1 + h @ W2 + b2
    tc_gemm<<<dim3(DD/128, MR/128), thr, TC_SMEM>>>(
        hbuf, W2T, out, MR, DD, FF, b2, X1, 1 | 2);
}

// round 8
// speedup vs baseline: 1.8699x; 1.7072x over previous
#include <cuda_runtime.h>
#include <cuda_fp16.h>
#include <math_constants.h>
#include <cstdint>

// Problem constants
#define BB 2
#define SS 2048
#define DD 1024
#define HH 16
#define DK 64
#define FF 4096
#define MR (BB*SS)          // 4096 rows
#define QKVN 3072

// ---------------- scratch (static device globals: alloc-free rule) ----------
__device__ __half g_nX16 [MR*DD];
__device__ __half g_qkv16[(size_t)MR*QKVN];
__device__ __half g_ctx16[MR*DD];
__device__ __half g_h16  [(size_t)MR*FF];
__device__ float  g_X1   [MR*DD];
__device__ __half g_WqkvT[(size_t)QKVN*DD];
__device__ __half g_WoT  [DD*DD];
__device__ __half g_W1T  [(size_t)DD*FF];
__device__ __half g_W2T  [(size_t)DD*FF];

// ---------------- small helpers ---------------------------------------------
__device__ __forceinline__ uint32_t smem_u32(const void* p) {
    uint32_t a;
    asm("{ .reg .u64 t; cvta.to.shared.u64 t, %1; cvt.u32.u64 %0, t; }"
        : "=r"(a) : "l"(p));
    return a;
}
__device__ __forceinline__ void cp16(uint32_t s, const void* g) {
    asm volatile("cp.async.cg.shared.global [%0], [%1], 16;" :: "r"(s), "l"(g));
}
__device__ __forceinline__ void ldsm4(uint32_t* r, uint32_t addr) {
    asm volatile(
        "ldmatrix.sync.aligned.m8n8.x4.shared.b16 {%0,%1,%2,%3}, [%4];"
        : "=r"(r[0]), "=r"(r[1]), "=r"(r[2]), "=r"(r[3]) : "r"(addr));
}
__device__ __forceinline__ void ldsm4t(uint32_t* r, uint32_t addr) {
    asm volatile(
        "ldmatrix.sync.aligned.m8n8.x4.trans.shared.b16 {%0,%1,%2,%3}, [%4];"
        : "=r"(r[0]), "=r"(r[1]), "=r"(r[2]), "=r"(r[3]) : "r"(addr));
}
__device__ __forceinline__ void mma_f16(float* c, const uint32_t* a,
                                        uint32_t b0, uint32_t b1) {
    asm volatile(
        "mma.sync.aligned.m16n8k16.row.col.f32.f16.f16.f32 "
        "{%0,%1,%2,%3}, {%4,%5,%6,%7}, {%8,%9}, {%0,%1,%2,%3};"
        : "+f"(c[0]), "+f"(c[1]), "+f"(c[2]), "+f"(c[3])
        : "r"(a[0]), "r"(a[1]), "r"(a[2]), "r"(a[3]), "r"(b0), "r"(b1));
}

// ---------------- weight transpose fp32 -> fp16 ------------------------------
// in: R x C row-major fp32 ; out: C x R row-major fp16
__global__ __launch_bounds__(256)
void transpose_h_kernel(const float* __restrict__ in, __half* __restrict__ out,
                        int R, int C)
{
    __shared__ float t[32][33];
    const int bx = blockIdx.x * 32, by = blockIdx.y * 32;
    const int tx = threadIdx.x & 31, ty = threadIdx.x >> 5;  // 32 x 8
    #pragma unroll
    for (int i = 0; i < 32; i += 8)
        t[ty + i][tx] = in[(size_t)(by + ty + i) * C + bx + tx];
    __syncthreads();
    #pragma unroll
    for (int i = 0; i < 32; i += 8)
        out[(size_t)(bx + ty + i) * R + by + tx] = __float2half_rn(t[tx][ty + i]);
}

// ---------------- LayerNorm (fp32 in, fp16 out) ------------------------------
__global__ __launch_bounds__(256)
void ln_kernel(const float* __restrict__ X, const float* __restrict__ g,
               const float* __restrict__ b, __half* __restrict__ Y)
{
    const int row = blockIdx.x;
    const int tid = threadIdx.x;
    const float4 x = ((const float4*)(X + (size_t)row * DD))[tid];

    float s  = x.x + x.y + x.z + x.w;
    float ss = x.x*x.x + x.y*x.y + x.z*x.z + x.w*x.w;
    #pragma unroll
    for (int o = 16; o; o >>= 1) {
        s  += __shfl_xor_sync(0xffffffffu, s,  o);
        ss += __shfl_xor_sync(0xffffffffu, ss, o);
    }
    __shared__ float sw[8], sw2[8];
    const int w = tid >> 5, ln = tid & 31;
    if (ln == 0) { sw[w] = s; sw2[w] = ss; }
    __syncthreads();
    float tot = 0.f, tot2 = 0.f;
    #pragma unroll
    for (int i = 0; i < 8; i++) { tot += sw[i]; tot2 += sw2[i]; }

    const float mean = tot * (1.0f / DD);
    const float var  = tot2 * (1.0f / DD) - mean * mean;
    const float rstd = rsqrtf(var + 1e-5f);

    const float4 gv = ((const float4*)g)[tid];
    const float4 bv = ((const float4*)b)[tid];
    __half2 h01 = __floats2half2_rn((x.x - mean) * rstd * gv.x + bv.x,
                                    (x.y - mean) * rstd * gv.y + bv.y);
    __half2 h23 = __floats2half2_rn((x.z - mean) * rstd * gv.z + bv.z,
                                    (x.w - mean) * rstd * gv.w + bv.w);
    __half2* yp = (__half2*)(Y + (size_t)row * DD + tid * 4);
    yp[0] = h01; yp[1] = h23;
}

// ---------------- fp16 mma.sync GEMM -----------------------------------------
// C = A[M,K] @ Bt[N,K]^T.  A,Bt fp16 row-major.  Output: C16 if non-null
// (fp16), else C (fp32).  mode: 1=+bias, 2=+resid (fp32), 4=relu
// CTA 128x128, warp 32x64, K-tile 64 halfs, 2-stage cp.async, occ 2.
#define KSTR 72                                  // halfs per smem row
#define TILEB (128 * KSTR * 2)                   // bytes per operand tile
#define STGB  (2 * TILEB)                        // stage bytes (A+B)
#define TC_SMEM (2 * STGB)                       // 73728 bytes

__global__ void __launch_bounds__(256, 2)
tc_gemm(const __half* __restrict__ A, const __half* __restrict__ Bt,
        float* __restrict__ C, __half* __restrict__ C16, int M, int N, int K,
        const float* __restrict__ bias, const float* __restrict__ resid,
        int mode)
{
    extern __shared__ __half smh[];
    const uint32_t sb = smem_u32(smh);

    const int tid  = threadIdx.x;
    const int wid  = tid >> 5, lane = tid & 31;
    const int tq   = lane >> 2, tr = lane & 3;
    const int wm   = (wid & 3) * 32;
    const int wn   = (wid >> 2) * 64;
    const int m0   = blockIdx.y * 128;
    const int n0   = blockIdx.x * 128;

    const int nk = K / 64;

    // ldmatrix lane base addresses (within stage 0)
    uint32_t a_addr[2];
    #pragma unroll
    for (int mt = 0; mt < 2; mt++) {
        const int row = wm + mt * 16 + (lane & 15);
        a_addr[mt] = sb + (uint32_t)(row * KSTR) * 2u + ((lane >> 4) << 4);
    }
    uint32_t b_addr[4];
    #pragma unroll
    for (int j = 0; j < 4; j++) {
        const int row = wn + j * 16 + (lane & 15);
        b_addr[j] = sb + TILEB + (uint32_t)(row * KSTR) * 2u + ((lane >> 4) << 4);
    }

    float acc[2][8][4];
    #pragma unroll
    for (int mt = 0; mt < 2; mt++)
        #pragma unroll
        for (int nt = 0; nt < 8; nt++)
            #pragma unroll
            for (int i = 0; i < 4; i++) acc[mt][nt][i] = 0.f;

    {
        const uint32_t sA = sb, sB = sb + TILEB;
        #pragma unroll
        for (int l = 0; l < 4; l++) {
            const int idx = tid + l * 256;          // 0..1023
            const int r = idx >> 3, c = idx & 7;    // 128 rows x 8 chunks
            cp16(sA + (uint32_t)(r * KSTR + c * 8) * 2u,
                 A + (size_t)(m0 + r) * K + c * 8);
            cp16(sB + (uint32_t)(r * KSTR + c * 8) * 2u,
                 Bt + (size_t)(n0 + r) * K + c * 8);
        }
        asm volatile("cp.async.commit_group;" ::: "memory");
    }

    for (int kt = 0; kt < nk; kt++) {
        if (kt + 1 < nk) {
            const int s = (kt + 1) & 1;
            const uint32_t sA = sb + (uint32_t)s * STGB;
            const uint32_t sB = sA + TILEB;
            const int kof = (kt + 1) * 64;
            #pragma unroll
            for (int l = 0; l < 4; l++) {
                const int idx = tid + l * 256;
                const int r = idx >> 3, c = idx & 7;
                cp16(sA + (uint32_t)(r * KSTR + c * 8) * 2u,
                     A + (size_t)(m0 + r) * K + kof + c * 8);
                cp16(sB + (uint32_t)(r * KSTR + c * 8) * 2u,
                     Bt + (size_t)(n0 + r) * K + kof + c * 8);
            }
            asm volatile("cp.async.commit_group;" ::: "memory");
            asm volatile("cp.async.wait_group 1;" ::: "memory");
        } else {
            asm volatile("cp.async.wait_group 0;" ::: "memory");
        }
        __syncthreads();

        const uint32_t stg = (uint32_t)(kt & 1) * STGB;

        #pragma unroll
        for (int ks = 0; ks < 4; ks++) {
            const uint32_t koff = stg + (uint32_t)ks * 32u;   // 16 halfs
            uint32_t a[2][4], bf[4][4];
            #pragma unroll
            for (int mt = 0; mt < 2; mt++)
                ldsm4(a[mt], a_addr[mt] + koff);
            #pragma unroll
            for (int j = 0; j < 4; j++)
                ldsm4(bf[j], b_addr[j] + koff);
            #pragma unroll
            for (int mt = 0; mt < 2; mt++)
                #pragma unroll
                for (int j = 0; j < 4; j++) {
                    mma_f16(acc[mt][2*j],   a[mt], bf[j][0], bf[j][2]);
                    mma_f16(acc[mt][2*j+1], a[mt], bf[j][1], bf[j][3]);
                }
        }
        __syncthreads();
    }

    #pragma unroll
    for (int mt = 0; mt < 2; mt++) {
        const int r0 = m0 + wm + mt * 16 + tq;
        #pragma unroll
        for (int half = 0; half < 2; half++) {
            const int m = r0 + half * 8;
            #pragma unroll
            for (int nt = 0; nt < 8; nt++) {
                const int n = n0 + wn + nt * 8 + tr * 2;
                float vx = acc[mt][nt][half * 2 + 0];
                float vy = acc[mt][nt][half * 2 + 1];
                if (mode & 1) {
                    const float2 bb = *(const float2*)(bias + n);
                    vx += bb.x; vy += bb.y;
                }
                if (mode & 2) {
                    const float2 rr = *(const float2*)(resid + (size_t)m * N + n);
                    vx += rr.x; vy += rr.y;
                }
                if (mode & 4) { vx = fmaxf(vx, 0.f); vy = fmaxf(vy, 0.f); }
                if (C16) {
                    *(__half2*)(C16 + (size_t)m * N + n) = __floats2half2_rn(vx, vy);
                } else {
                    float2 o; o.x = vx; o.y = vy;
                    *(float2*)(C + (size_t)m * N + n) = o;
                }
            }
        }
    }
}

// ---------------- Flash attention, fp16 tensor cores -------------------------
// 8 warps, 128 q-rows/CTA, k-tiles of 64. Smem stride 72 halfs everywhere.
#define ASH 72
#define ATT_SMEM ((128*ASH + 64*ASH + 64*ASH + 128*ASH) * 2)   // 55296 B

__global__ __launch_bounds__(256, 2)
void attn_mma_kernel(const __half* __restrict__ QKVg, __half* __restrict__ Og,
                     int ldi)
{
    extern __shared__ __half smh[];
    __half* Qs = smh;                     // [128][72]
    __half* Ks = smh + 128 * ASH;         // [64][72]  rows = seq_k, cols = d
    __half* Vs = Ks + 64 * ASH;           // [64][72]  rows = seq_k, cols = d
    __half* Ps = Vs + 64 * ASH;           // [128][72] warp-private 16-row slabs

    const int tid  = threadIdx.x;
    const int wid  = tid >> 5, lane = tid & 31;
    const int tq   = lane >> 2, tr = lane & 3;
    const int wq0  = wid * 16;
    const int bh   = blockIdx.y;
    const int b    = bh >> 4, h = bh & 15;
    const size_t base_i = (size_t)b * SS * ldi + (size_t)h * DK;
    const size_t base_o = (size_t)b * SS * DD + (size_t)h * DK;
    const int q0   = blockIdx.x * 128;

    const __half* Qg = QKVg + base_i;
    const __half* Kg = QKVg + base_i + DD;
    const __half* Vg = QKVg + base_i + 2 * DD;

    const uint32_t sQ = smem_u32(Qs);
    const uint32_t sK = smem_u32(Ks);
    const uint32_t sV = smem_u32(Vs);
    const uint32_t sP = smem_u32(Ps);

    // ldmatrix lane base addresses
    const uint32_t qa = sQ + (uint32_t)((wq0 + (lane & 15)) * ASH) * 2u
                      + ((lane >> 4) << 4);
    const uint32_t pa = sP + (uint32_t)((wq0 + (lane & 15)) * ASH) * 2u
                      + ((lane >> 4) << 4);
    uint32_t ka[4], va[4];
    #pragma unroll
    for (int j = 0; j < 4; j++) {
        ka[j] = sK + (uint32_t)((j * 16 + (lane & 15)) * ASH) * 2u
              + ((lane >> 4) << 4);
        va[j] = sV + (uint32_t)((lane & 15) * ASH) * 2u
              + (uint32_t)(j * 16 + ((lane >> 4) << 3)) * 2u;
    }

    // load Q tile (scaled by exact 1/8)
    const __half2 sc2 = __float2half2_rn(0.125f);
    #pragma unroll
    for (int l = 0; l < 4; l++) {
        const int idx = tid + l * 256;          // 0..1023
        const int r = idx >> 3, c = idx & 7;
        uint4 u = *(const uint4*)(Qg + (size_t)(q0 + r) * ldi + c * 8);
        __half2* p = (__half2*)&u;
        p[0] = __hmul2(p[0], sc2); p[1] = __hmul2(p[1], sc2);
        p[2] = __hmul2(p[2], sc2); p[3] = __hmul2(p[3], sc2);
        *(uint4*)(Qs + r * ASH + c * 8) = u;
    }

    float m_[2], l_[2], o[8][4];
    m_[0] = m_[1] = -CUDART_INF_F;
    l_[0] = l_[1] = 0.f;
    #pragma unroll
    for (int nt = 0; nt < 8; nt++)
        #pragma unroll
        for (int i = 0; i < 4; i++) o[nt][i] = 0.f;

    for (int kt = 0; kt < SS / 64; kt++) {
        __syncthreads();                       // prior PV done with Ks/Vs
        const int kb = kt * 64;
        #pragma unroll
        for (int l = 0; l < 2; l++) {          // K tile: 64 rows x 8 chunks
            const int idx = tid + l * 256;
            const int r = idx >> 3, c = idx & 7;
            *(uint4*)(Ks + r * ASH + c * 8) =
                *(const uint4*)(Kg + (size_t)(kb + r) * ldi + c * 8);
        }
        #pragma unroll
        for (int l = 0; l < 2; l++) {          // V tile
            const int idx = tid + l * 256;
            const int r = idx >> 3, c = idx & 7;
            *(uint4*)(Vs + r * ASH + c * 8) =
                *(const uint4*)(Vg + (size_t)(kb + r) * ldi + c * 8);
        }
        __syncthreads();

        // S = Q @ K^T
        float s[8][4];
        #pragma unroll
        for (int nt = 0; nt < 8; nt++)
            #pragma unroll
            for (int i = 0; i < 4; i++) s[nt][i] = 0.f;

        #pragma unroll
        for (int ks = 0; ks < 4; ks++) {
            const uint32_t koff = (uint32_t)ks * 32u;
            uint32_t a[4];
            ldsm4(a, qa + koff);
            #pragma unroll
            for (int j = 0; j < 4; j++) {
                uint32_t kf[4];
                ldsm4(kf, ka[j] + koff);
                mma_f16(s[2*j],   a, kf[0], kf[2]);
                mma_f16(s[2*j+1], a, kf[1], kf[3]);
            }
        }

        // online softmax in fragment layout (rows tq, tq+8)
        #pragma unroll
        for (int half = 0; half < 2; half++) {
            float mx = -CUDART_INF_F;
            #pragma unroll
            for (int nt = 0; nt < 8; nt++)
                mx = fmaxf(mx, fmaxf(s[nt][half * 2], s[nt][half * 2 + 1]));
            mx = fmaxf(mx, __shfl_xor_sync(0xffffffffu, mx, 1));
            mx = fmaxf(mx, __shfl_xor_sync(0xffffffffu, mx, 2));
            const float mn   = fmaxf(m_[half], mx);
            const float corr = __expf(m_[half] - mn);
            m_[half] = mn;
            float sum = 0.f;
            #pragma unroll
            for (int nt = 0; nt < 8; nt++) {
                float p0 = __expf(s[nt][half * 2]     - mn);
                float p1 = __expf(s[nt][half * 2 + 1] - mn);
                s[nt][half * 2]     = p0;
                s[nt][half * 2 + 1] = p1;
                sum += p0 + p1;
            }
            sum += __shfl_xor_sync(0xffffffffu, sum, 1);
            sum += __shfl_xor_sync(0xffffffffu, sum, 2);
            l_[half] = l_[half] * corr + sum;
            #pragma unroll
            for (int nt = 0; nt < 8; nt++) {
                o[nt][half * 2]     *= corr;
                o[nt][half * 2 + 1] *= corr;
            }
        }

        // store P slab (fp16, warp-private rows)
        #pragma unroll
        for (int nt = 0; nt < 8; nt++) {
            const int col = nt * 8 + tr * 2;
            *(__half2*)(Ps + (wq0 + tq) * ASH + col) =
                __floats2half2_rn(s[nt][0], s[nt][1]);
            *(__half2*)(Ps + (wq0 + tq + 8) * ASH + col) =
                __floats2half2_rn(s[nt][2], s[nt][3]);
        }
        __syncwarp();

        // O += P @ V   (V via ldmatrix.trans: B from [k][n] rows)
        #pragma unroll
        for (int ks = 0; ks < 4; ks++) {
            uint32_t a[4];
            ldsm4(a, pa + (uint32_t)ks * 32u);
            const uint32_t voff = (uint32_t)ks * (16u * ASH * 2u);
            #pragma unroll
            for (int j = 0; j < 4; j++) {
                uint32_t vf[4];
                ldsm4t(vf, va[j] + voff);
                mma_f16(o[2*j],   a, vf[0], vf[1]);
                mma_f16(o[2*j+1], a, vf[2], vf[3]);
            }
        }
    }

    // normalize + store ctx fp16
    const float inv0 = 1.0f / l_[0];
    const float inv1 = 1.0f / l_[1];
    #pragma unroll
    for (int nt = 0; nt < 8; nt++) {
        const int col = nt * 8 + tr * 2;
        *(__half2*)(Og + base_o + (size_t)(q0 + wq0 + tq) * DD + col) =
            __floats2half2_rn(o[nt][0] * inv0, o[nt][1] * inv0);
        *(__half2*)(Og + base_o + (size_t)(q0 + wq0 + tq + 8) * DD + col) =
            __floats2half2_rn(o[nt][2] * inv1, o[nt][3] * inv1);
    }
}

// ---------------- launch -----------------------------------------------------
extern "C" void kernel_launch(void* const* d_in, const int* in_sizes, int n_in,
                              void* d_out, int out_size)
{
    const float* X   = (const float*)d_in[0];
    const float* Wq  = (const float*)d_in[1];
    const float* Wk  = (const float*)d_in[2];
    const float* Wv  = (const float*)d_in[3];
    const float* Wo  = (const float*)d_in[4];
    const float* W1  = (const float*)d_in[5];
    const float* b1  = (const float*)d_in[6];
    const float* W2  = (const float*)d_in[7];
    const float* b2  = (const float*)d_in[8];
    const float* g1  = (const float*)d_in[9];
    const float* be1 = (const float*)d_in[10];
    const float* g2  = (const float*)d_in[11];
    const float* be2 = (const float*)d_in[12];
    float* out = (float*)d_out;

    __half *nX16, *qkv16, *ctx16, *h16, *WqkvT, *WoT, *W1T, *W2T;
    float *X1;
    cudaGetSymbolAddress((void**)&nX16,  g_nX16);
    cudaGetSymbolAddress((void**)&qkv16, g_qkv16);
    cudaGetSymbolAddress((void**)&ctx16, g_ctx16);
    cudaGetSymbolAddress((void**)&h16,   g_h16);
    cudaGetSymbolAddress((void**)&X1,    g_X1);
    cudaGetSymbolAddress((void**)&WqkvT, g_WqkvT);
    cudaGetSymbolAddress((void**)&WoT,   g_WoT);
    cudaGetSymbolAddress((void**)&W1T,   g_W1T);
    cudaGetSymbolAddress((void**)&W2T,   g_W2T);

    cudaFuncSetAttribute(tc_gemm, cudaFuncAttributeMaxDynamicSharedMemorySize,
                         TC_SMEM);
    cudaFuncSetAttribute(attn_mma_kernel,
                         cudaFuncAttributeMaxDynamicSharedMemorySize, ATT_SMEM);

    dim3 thr(256);

    // weight transposes (fp32 -> fp16, rne)
    transpose_h_kernel<<<dim3(DD/32, DD/32), thr>>>(Wq, WqkvT, DD, DD);
    transpose_h_kernel<<<dim3(DD/32, DD/32), thr>>>(Wk, WqkvT + DD*DD, DD, DD);
    transpose_h_kernel<<<dim3(DD/32, DD/32), thr>>>(Wv, WqkvT + 2*DD*DD, DD, DD);
    transpose_h_kernel<<<dim3(DD/32, DD/32), thr>>>(Wo, WoT, DD, DD);
    transpose_h_kernel<<<dim3(FF/32, DD/32), thr>>>(W1, W1T, DD, FF);
    transpose_h_kernel<<<dim3(DD/32, FF/32), thr>>>(W2, W2T, FF, DD);

    // LN1
    ln_kernel<<<MR, thr>>>(X, g1, be1, nX16);

    // fused QKV projection -> fp16
    tc_gemm<<<dim3(QKVN/128, MR/128), thr, TC_SMEM>>>(
        nX16, WqkvT, nullptr, qkv16, MR, QKVN, DD, nullptr, nullptr, 0);

    // attention (fp16 tensor-core flash) -> ctx fp16
    attn_mma_kernel<<<dim3(SS/128, BB*HH), thr, ATT_SMEM>>>(qkv16, ctx16, QKVN);

    // output projection + residual -> X1 fp32
    tc_gemm<<<dim3(DD/128, MR/128), thr, TC_SMEM>>>(
        ctx16, WoT, X1, nullptr, MR, DD, DD, nullptr, X, 2);

    // LN2
    ln_kernel<<<MR, thr>>>(X1, g2, be2, nX16);

    // FFN up: h = relu(nX @ W1 + b1) -> fp16
    tc_gemm<<<dim3(FF/128, MR/128), thr, TC_SMEM>>>(
        nX16, W1T, nullptr, h16, MR, FF, DD, b1, nullptr, 1 | 4);

    // FFN down + residual: out = X1 + h @ W2 + b2 (fp32)
    tc_gemm<<<dim3(DD/128, MR/128), thr, TC_SMEM>>>(
        h16, W2T, out, nullptr, MR, DD, FF, b2, X1, 1 | 2);
}

// round 10
// speedup vs baseline: 2.0259x; 1.0834x over previous
#include <cuda_runtime.h>
#include <cuda_fp16.h>
#include <math_constants.h>
#include <cstdint>

// Problem constants
#define BB 2
#define SS 2048
#define DD 1024
#define HH 16
#define DK 64
#define FF 4096
#define MR (BB*SS)          // 4096 rows
#define QKVN 3072

// ---------------- scratch (static device globals: alloc-free rule) ----------
__device__ __half g_nX16  [MR*DD];
__device__ __half g_qkv16 [(size_t)MR*QKVN];
__device__ __half g_ctx16 [MR*DD];
__device__ __half g_h16   [(size_t)MR*FF];
__device__ float  g_X1    [MR*DD];
__device__ __half g_Wqkv16[(size_t)DD*QKVN];   // [K=1024, N=3072]
__device__ __half g_Wo16  [DD*DD];             // [K=1024, N=1024]
__device__ __half g_W1h   [(size_t)DD*FF];     // [K=1024, N=4096]
__device__ __half g_W2h   [(size_t)FF*DD];     // [K=4096, N=1024]

// ---------------- small helpers ---------------------------------------------
__device__ __forceinline__ uint32_t smem_u32(const void* p) {
    uint32_t a;
    asm("{ .reg .u64 t; cvta.to.shared.u64 t, %1; cvt.u32.u64 %0, t; }"
        : "=r"(a) : "l"(p));
    return a;
}
__device__ __forceinline__ void cp16(uint32_t s, const void* g) {
    asm volatile("cp.async.cg.shared.global [%0], [%1], 16;" :: "r"(s), "l"(g));
}
__device__ __forceinline__ void ldsm4(uint32_t* r, uint32_t addr) {
    asm volatile(
        "ldmatrix.sync.aligned.m8n8.x4.shared.b16 {%0,%1,%2,%3}, [%4];"
        : "=r"(r[0]), "=r"(r[1]), "=r"(r[2]), "=r"(r[3]) : "r"(addr));
}
__device__ __forceinline__ void ldsm4t(uint32_t* r, uint32_t addr) {
    asm volatile(
        "ldmatrix.sync.aligned.m8n8.x4.trans.shared.b16 {%0,%1,%2,%3}, [%4];"
        : "=r"(r[0]), "=r"(r[1]), "=r"(r[2]), "=r"(r[3]) : "r"(addr));
}
__device__ __forceinline__ void mma_f16(float* c, const uint32_t* a,
                                        uint32_t b0, uint32_t b1) {
    asm volatile(
        "mma.sync.aligned.m16n8k16.row.col.f32.f16.f16.f32 "
        "{%0,%1,%2,%3}, {%4,%5,%6,%7}, {%8,%9}, {%0,%1,%2,%3};"
        : "+f"(c[0]), "+f"(c[1]), "+f"(c[2]), "+f"(c[3])
        : "r"(a[0]), "r"(a[1]), "r"(a[2]), "r"(a[3]), "r"(b0), "r"(b1));
}

// ---------------- fp32 -> fp16 convert (layout-preserving, strided dst) ------
__global__ __launch_bounds__(256)
void convert_h_kernel(const float* __restrict__ in, __half* __restrict__ out,
                      int rows, int cols, int ldo, int coff)
{
    const int n4 = rows * (cols >> 2);
    for (int idx = blockIdx.x * 256 + threadIdx.x; idx < n4;
         idx += gridDim.x * 256) {
        const int r  = idx / (cols >> 2);
        const int c4 = (idx - r * (cols >> 2)) << 2;
        const float4 v = *(const float4*)(in + (size_t)r * cols + c4);
        __half2* o = (__half2*)(out + (size_t)r * ldo + coff + c4);
        o[0] = __floats2half2_rn(v.x, v.y);
        o[1] = __floats2half2_rn(v.z, v.w);
    }
}

// ---------------- LayerNorm (fp32 in, fp16 out) ------------------------------
__global__ __launch_bounds__(256)
void ln_kernel(const float* __restrict__ X, const float* __restrict__ g,
               const float* __restrict__ b, __half* __restrict__ Y)
{
    const int row = blockIdx.x;
    const int tid = threadIdx.x;
    const float4 x = ((const float4*)(X + (size_t)row * DD))[tid];

    float s  = x.x + x.y + x.z + x.w;
    float ss = x.x*x.x + x.y*x.y + x.z*x.z + x.w*x.w;
    #pragma unroll
    for (int o = 16; o; o >>= 1) {
        s  += __shfl_xor_sync(0xffffffffu, s,  o);
        ss += __shfl_xor_sync(0xffffffffu, ss, o);
    }
    __shared__ float sw[8], sw2[8];
    const int w = tid >> 5, ln = tid & 31;
    if (ln == 0) { sw[w] = s; sw2[w] = ss; }
    __syncthreads();
    float tot = 0.f, tot2 = 0.f;
    #pragma unroll
    for (int i = 0; i < 8; i++) { tot += sw[i]; tot2 += sw2[i]; }

    const float mean = tot * (1.0f / DD);
    const float var  = tot2 * (1.0f / DD) - mean * mean;
    const float rstd = rsqrtf(var + 1e-5f);

    const float4 gv = ((const float4*)g)[tid];
    const float4 bv = ((const float4*)b)[tid];
    __half2 h01 = __floats2half2_rn((x.x - mean) * rstd * gv.x + bv.x,
                                    (x.y - mean) * rstd * gv.y + bv.y);
    __half2 h23 = __floats2half2_rn((x.z - mean) * rstd * gv.z + bv.z,
                                    (x.w - mean) * rstd * gv.w + bv.w);
    __half2* yp = (__half2*)(Y + (size_t)row * DD + tid * 4);
    yp[0] = h01; yp[1] = h23;
}

// ---------------- fp16 mma.sync GEMM, B in [K,N] via ldmatrix.trans ----------
// C = A[M,K] @ B[K,N].  mode: 1=+bias, 2=+resid(fp32), 4=relu.  C16 or C out.
// CTA 128x128, warp 32x64, K-tile 64, 3-stage cp.async, 1 bar/tile, occ 2.
#define AKSTR 72                                 // A smem row stride (halfs)
#define BNSTR 136                                // B smem row stride (halfs)
#define ATILEB (128 * AKSTR * 2)                 // 18432 B
#define BTILEB (64 * BNSTR * 2)                  // 17408 B
#define STGB   (ATILEB + BTILEB)                 // 35840 B
#define TC_SMEM (3 * STGB)                       // 107520 B

__global__ void __launch_bounds__(256, 2)
tc_gemm(const __half* __restrict__ A, const __half* __restrict__ B,
        float* __restrict__ C, __half* __restrict__ C16, int M, int N, int K,
        const float* __restrict__ bias, const float* __restrict__ resid,
        int mode)
{
    extern __shared__ __half smh[];
    const uint32_t sb = smem_u32(smh);

    const int tid  = threadIdx.x;
    const int wid  = tid >> 5, lane = tid & 31;
    const int tq   = lane >> 2, tr = lane & 3;
    const int wm   = (wid & 3) * 32;
    const int wn   = (wid >> 2) * 64;
    const int m0   = blockIdx.y * 128;
    const int n0   = blockIdx.x * 128;

    const int nk = K / 64;

    // ldmatrix lane base offsets (within one stage)
    uint32_t a_off[2];
    #pragma unroll
    for (int mt = 0; mt < 2; mt++) {
        const int row = wm + mt * 16 + (lane & 15);
        a_off[mt] = (uint32_t)(row * AKSTR) * 2u + ((lane >> 4) << 4);
    }
    uint32_t b_off[4];
    #pragma unroll
    for (int j = 0; j < 4; j++) {
        const int col = wn + j * 16 + ((lane >> 4) << 3);
        b_off[j] = ATILEB + (uint32_t)((lane & 15) * BNSTR + col) * 2u;
    }

    float acc[2][8][4];
    #pragma unroll
    for (int mt = 0; mt < 2; mt++)
        #pragma unroll
        for (int nt = 0; nt < 8; nt++)
            #pragma unroll
            for (int i = 0; i < 4; i++) acc[mt][nt][i] = 0.f;

    // stage loader: A 128x64 (idx>>3, idx&7), B 64x128 (idx>>4, idx&15)
    auto issue_stage = [&](int kt) {
        const uint32_t sA = sb + (uint32_t)(kt % 3) * STGB;
        const uint32_t sB = sA + ATILEB;
        const int kof = kt * 64;
        #pragma unroll
        for (int l = 0; l < 4; l++) {
            const int idx = tid + l * 256;
            const int r = idx >> 3, c = idx & 7;
            cp16(sA + (uint32_t)(r * AKSTR + c * 8) * 2u,
                 A + (size_t)(m0 + r) * K + kof + c * 8);
        }
        #pragma unroll
        for (int l = 0; l < 4; l++) {
            const int idx = tid + l * 256;
            const int r = idx >> 4, c = idx & 15;
            cp16(sB + (uint32_t)(r * BNSTR + c * 8) * 2u,
                 B + (size_t)(kof + r) * N + n0 + c * 8);
        }
        asm volatile("cp.async.commit_group;" ::: "memory");
    };

    issue_stage(0);
    issue_stage(1);

    for (int kt = 0; kt < nk; kt++) {
        if (kt < nk - 1)
            asm volatile("cp.async.wait_group 1;" ::: "memory");
        else
            asm volatile("cp.async.wait_group 0;" ::: "memory");
        __syncthreads();

        if (kt + 2 < nk) issue_stage(kt + 2);

        const uint32_t stg = (uint32_t)(kt % 3) * STGB;

        #pragma unroll
        for (int ks = 0; ks < 4; ks++) {
            uint32_t a[2][4], bf[4][4];
            const uint32_t akoff = stg + (uint32_t)ks * 32u;            // 16 halfs
            const uint32_t bkoff = stg + (uint32_t)ks * (16u * BNSTR * 2u);
            #pragma unroll
            for (int mt = 0; mt < 2; mt++)
                ldsm4(a[mt], sb + a_off[mt] + akoff);
            #pragma unroll
            for (int j = 0; j < 4; j++)
                ldsm4t(bf[j], sb + b_off[j] + bkoff);
            #pragma unroll
            for (int mt = 0; mt < 2; mt++)
                #pragma unroll
                for (int j = 0; j < 4; j++) {
                    mma_f16(acc[mt][2*j],   a[mt], bf[j][0], bf[j][1]);
                    mma_f16(acc[mt][2*j+1], a[mt], bf[j][2], bf[j][3]);
                }
        }
        __syncthreads();
    }

    #pragma unroll
    for (int mt = 0; mt < 2; mt++) {
        const int r0 = m0 + wm + mt * 16 + tq;
        #pragma unroll
        for (int half = 0; half < 2; half++) {
            const int m = r0 + half * 8;
            #pragma unroll
            for (int nt = 0; nt < 8; nt++) {
                const int n = n0 + wn + nt * 8 + tr * 2;
                float vx = acc[mt][nt][half * 2 + 0];
                float vy = acc[mt][nt][half * 2 + 1];
                if (mode & 1) {
                    const float2 bb = *(const float2*)(bias + n);
                    vx += bb.x; vy += bb.y;
                }
                if (mode & 2) {
                    const float2 rr = *(const float2*)(resid + (size_t)m * N + n);
                    vx += rr.x; vy += rr.y;
                }
                if (mode & 4) { vx = fmaxf(vx, 0.f); vy = fmaxf(vy, 0.f); }
                if (C16) {
                    *(__half2*)(C16 + (size_t)m * N + n) = __floats2half2_rn(vx, vy);
                } else {
                    float2 o; o.x = vx; o.y = vy;
                    *(float2*)(C + (size_t)m * N + n) = o;
                }
            }
        }
    }
}

// ---------------- Flash attention, fp16 tensor cores, async K/V --------------
// 8 warps, 128 q-rows/CTA, k-tiles of 64, double-buffered K/V via cp.async.
#define ASH 72
#define KVBUFH (64 * ASH)                          // halfs per K or V buffer
#define ATT_SMEM ((128*ASH + 2*KVBUFH + 2*KVBUFH + 128*ASH) * 2)   // 73728 B

__global__ __launch_bounds__(256, 2)
void attn_mma_kernel(const __half* __restrict__ QKVg, __half* __restrict__ Og,
                     int ldi)
{
    extern __shared__ __half smh[];
    __half* Qs  = smh;                       // [128][72]
    __half* Ks0 = smh + 128 * ASH;           // 2 x [64][72]
    __half* Vs0 = Ks0 + 2 * KVBUFH;          // 2 x [64][72]
    __half* Ps  = Vs0 + 2 * KVBUFH;          // [128][72]

    const int tid  = threadIdx.x;
    const int wid  = tid >> 5, lane = tid & 31;
    const int tq   = lane >> 2, tr = lane & 3;
    const int wq0  = wid * 16;
    const int bh   = blockIdx.y;
    const int b    = bh >> 4, h = bh & 15;
    const size_t base_i = (size_t)b * SS * ldi + (size_t)h * DK;
    const size_t base_o = (size_t)b * SS * DD + (size_t)h * DK;
    const int q0   = blockIdx.x * 128;

    const __half* Qg = QKVg + base_i;
    const __half* Kg = QKVg + base_i + DD;
    const __half* Vg = QKVg + base_i + 2 * DD;

    const uint32_t sQ = smem_u32(Qs);
    const uint32_t sK = smem_u32(Ks0);
    const uint32_t sV = smem_u32(Vs0);
    const uint32_t sP = smem_u32(Ps);

    const uint32_t qa = sQ + (uint32_t)((wq0 + (lane & 15)) * ASH) * 2u
                      + ((lane >> 4) << 4);
    const uint32_t pa = sP + (uint32_t)((wq0 + (lane & 15)) * ASH) * 2u
                      + ((lane >> 4) << 4);
    uint32_t ka_off[4], va_off[4];
    #pragma unroll
    for (int j = 0; j < 4; j++) {
        ka_off[j] = (uint32_t)((j * 16 + (lane & 15)) * ASH) * 2u
                  + ((lane >> 4) << 4);
        va_off[j] = (uint32_t)((lane & 15) * ASH) * 2u
                  + (uint32_t)(j * 16 + ((lane >> 4) << 3)) * 2u;
    }

    // load Q tile (scaled by exact 1/8)
    const __half2 sc2 = __float2half2_rn(0.125f);
    #pragma unroll
    for (int l = 0; l < 4; l++) {
        const int idx = tid + l * 256;
        const int r = idx >> 3, c = idx & 7;
        uint4 u = *(const uint4*)(Qg + (size_t)(q0 + r) * ldi + c * 8);
        __half2* p = (__half2*)&u;
        p[0] = __hmul2(p[0], sc2); p[1] = __hmul2(p[1], sc2);
        p[2] = __hmul2(p[2], sc2); p[3] = __hmul2(p[3], sc2);
        *(uint4*)(Qs + r * ASH + c * 8) = u;
    }

    // async K/V tile loader (64 rows x 8 chunks each)
    auto issue_kv = [&](int kt) {
        const uint32_t kb_ = sK + (uint32_t)(kt & 1) * (KVBUFH * 2u);
        const uint32_t vb_ = sV + (uint32_t)(kt & 1) * (KVBUFH * 2u);
        const int kb = kt * 64;
        #pragma unroll
        for (int l = 0; l < 2; l++) {
            const int idx = tid + l * 256;
            const int r = idx >> 3, c = idx & 7;
            cp16(kb_ + (uint32_t)(r * ASH + c * 8) * 2u,
                 Kg + (size_t)(kb + r) * ldi + c * 8);
        }
        #pragma unroll
        for (int l = 0; l < 2; l++) {
            const int idx = tid + l * 256;
            const int r = idx >> 3, c = idx & 7;
            cp16(vb_ + (uint32_t)(r * ASH + c * 8) * 2u,
                 Vg + (size_t)(kb + r) * ldi + c * 8);
        }
        asm volatile("cp.async.commit_group;" ::: "memory");
    };

    issue_kv(0);

    float m_[2], l_[2], o[8][4];
    m_[0] = m_[1] = -CUDART_INF_F;
    l_[0] = l_[1] = 0.f;
    #pragma unroll
    for (int nt = 0; nt < 8; nt++)
        #pragma unroll
        for (int i = 0; i < 4; i++) o[nt][i] = 0.f;

    const int ntiles = SS / 64;
    for (int kt = 0; kt < ntiles; kt++) {
        asm volatile("cp.async.wait_group 0;" ::: "memory");
        __syncthreads();
        if (kt + 1 < ntiles) issue_kv(kt + 1);

        const uint32_t bufb = (uint32_t)(kt & 1) * (KVBUFH * 2u);

        // S = Q @ K^T
        float s[8][4];
        #pragma unroll
        for (int nt = 0; nt < 8; nt++)
            #pragma unroll
            for (int i = 0; i < 4; i++) s[nt][i] = 0.f;

        #pragma unroll
        for (int ks = 0; ks < 4; ks++) {
            const uint32_t koff = (uint32_t)ks * 32u;
            uint32_t a[4];
            ldsm4(a, qa + koff);
            #pragma unroll
            for (int j = 0; j < 4; j++) {
                uint32_t kf[4];
                ldsm4(kf, sK + bufb + ka_off[j] + koff);
                mma_f16(s[2*j],   a, kf[0], kf[2]);
                mma_f16(s[2*j+1], a, kf[1], kf[3]);
            }
        }

        // online softmax in fragment layout (rows tq, tq+8)
        #pragma unroll
        for (int half = 0; half < 2; half++) {
            float mx = -CUDART_INF_F;
            #pragma unroll
            for (int nt = 0; nt < 8; nt++)
                mx = fmaxf(mx, fmaxf(s[nt][half * 2], s[nt][half * 2 + 1]));
            mx = fmaxf(mx, __shfl_xor_sync(0xffffffffu, mx, 1));
            mx = fmaxf(mx, __shfl_xor_sync(0xffffffffu, mx, 2));
            const float mn   = fmaxf(m_[half], mx);
            const float corr = __expf(m_[half] - mn);
            m_[half] = mn;
            float sum = 0.f;
            #pragma unroll
            for (int nt = 0; nt < 8; nt++) {
                float p0 = __expf(s[nt][half * 2]     - mn);
                float p1 = __expf(s[nt][half * 2 + 1] - mn);
                s[nt][half * 2]     = p0;
                s[nt][half * 2 + 1] = p1;
                sum += p0 + p1;
            }
            sum += __shfl_xor_sync(0xffffffffu, sum, 1);
            sum += __shfl_xor_sync(0xffffffffu, sum, 2);
            l_[half] = l_[half] * corr + sum;
            #pragma unroll
            for (int nt = 0; nt < 8; nt++) {
                o[nt][half * 2]     *= corr;
                o[nt][half * 2 + 1] *= corr;
            }
        }

        // store P slab (fp16, warp-private rows)
        #pragma unroll
        for (int nt = 0; nt < 8; nt++) {
            const int col = nt * 8 + tr * 2;
            *(__half2*)(Ps + (wq0 + tq) * ASH + col) =
                __floats2half2_rn(s[nt][0], s[nt][1]);
            *(__half2*)(Ps + (wq0 + tq + 8) * ASH + col) =
                __floats2half2_rn(s[nt][2], s[nt][3]);
        }
        __syncwarp();

        // O += P @ V   (V via ldmatrix.trans)
        #pragma unroll
        for (int ks = 0; ks < 4; ks++) {
            uint32_t a[4];
            ldsm4(a, pa + (uint32_t)ks * 32u);
            const uint32_t voff = bufb + (uint32_t)ks * (16u * ASH * 2u);
            #pragma unroll
            for (int j = 0; j < 4; j++) {
                uint32_t vf[4];
                ldsm4t(vf, sV + voff + va_off[j]);
                mma_f16(o[2*j],   a, vf[0], vf[1]);
                mma_f16(o[2*j+1], a, vf[2], vf[3]);
            }
        }
    }

    // normalize + store ctx fp16
    const float inv0 = 1.0f / l_[0];
    const float inv1 = 1.0f / l_[1];
    #pragma unroll
    for (int nt = 0; nt < 8; nt++) {
        const int col = nt * 8 + tr * 2;
        *(__half2*)(Og + base_o + (size_t)(q0 + wq0 + tq) * DD + col) =
            __floats2half2_rn(o[nt][0] * inv0, o[nt][1] * inv0);
        *(__half2*)(Og + base_o + (size_t)(q0 + wq0 + tq + 8) * DD + col) =
            __floats2half2_rn(o[nt][2] * inv1, o[nt][3] * inv1);
    }
}

// ---------------- launch -----------------------------------------------------
extern "C" void kernel_launch(void* const* d_in, const int* in_sizes, int n_in,
                              void* d_out, int out_size)
{
    const float* X   = (const float*)d_in[0];
    const float* Wq  = (const float*)d_in[1];
    const float* Wk  = (const float*)d_in[2];
    const float* Wv  = (const float*)d_in[3];
    const float* Wo  = (const float*)d_in[4];
    const float* W1  = (const float*)d_in[5];
    const float* b1  = (const float*)d_in[6];
    const float* W2  = (const float*)d_in[7];
    const float* b2  = (const float*)d_in[8];
    const float* g1  = (const float*)d_in[9];
    const float* be1 = (const float*)d_in[10];
    const float* g2  = (const float*)d_in[11];
    const float* be2 = (const float*)d_in[12];
    float* out = (float*)d_out;

    __half *nX16, *qkv16, *ctx16, *h16, *Wqkv16, *Wo16, *W1h, *W2h;
    float *X1;
    cudaGetSymbolAddress((void**)&nX16,   g_nX16);
    cudaGetSymbolAddress((void**)&qkv16,  g_qkv16);
    cudaGetSymbolAddress((void**)&ctx16,  g_ctx16);
    cudaGetSymbolAddress((void**)&h16,    g_h16);
    cudaGetSymbolAddress((void**)&X1,     g_X1);
    cudaGetSymbolAddress((void**)&Wqkv16, g_Wqkv16);
    cudaGetSymbolAddress((void**)&Wo16,   g_Wo16);
    cudaGetSymbolAddress((void**)&W1h,    g_W1h);
    cudaGetSymbolAddress((void**)&W2h,    g_W2h);

    cudaFuncSetAttribute(tc_gemm, cudaFuncAttributeMaxDynamicSharedMemorySize,
                         TC_SMEM);
    cudaFuncSetAttribute(attn_mma_kernel,
                         cudaFuncAttributeMaxDynamicSharedMemorySize, ATT_SMEM);

    dim3 thr(256);

    // weight converts (layout-preserving [K,N], fp32 -> fp16)
    convert_h_kernel<<<1024, thr>>>(Wq, Wqkv16, DD, DD, QKVN, 0);
    convert_h_kernel<<<1024, thr>>>(Wk, Wqkv16, DD, DD, QKVN, DD);
    convert_h_kernel<<<1024, thr>>>(Wv, Wqkv16, DD, DD, QKVN, 2*DD);
    convert_h_kernel<<<1024, thr>>>(Wo, Wo16, DD, DD, DD, 0);
    convert_h_kernel<<<2048, thr>>>(W1, W1h, DD, FF, FF, 0);
    convert_h_kernel<<<2048, thr>>>(W2, W2h, FF, DD, DD, 0);

    // LN1
    ln_kernel<<<MR, thr>>>(X, g1, be1, nX16);

    // fused QKV projection -> fp16
    tc_gemm<<<dim3(QKVN/128, MR/128), thr, TC_SMEM>>>(
        nX16, Wqkv16, nullptr, qkv16, MR, QKVN, DD, nullptr, nullptr, 0);

    // attention (fp16 tensor-core flash) -> ctx fp16
    attn_mma_kernel<<<dim3(SS/128, BB*HH), thr, ATT_SMEM>>>(qkv16, ctx16, QKVN);

    // output projection + residual -> X1 fp32
    tc_gemm<<<dim3(DD/128, MR/128), thr, TC_SMEM>>>(
        ctx16, Wo16, X1, nullptr, MR, DD, DD, nullptr, X, 2);

    // LN2
    ln_kernel<<<MR, thr>>>(X1, g2, be2, nX16);

    // FFN up: h = relu(nX @ W1 + b1) -> fp16
    tc_gemm<<<dim3(FF/128, MR/128), thr, TC_SMEM>>>(
        nX16, W1h, nullptr, h16, MR, FF, DD, b1, nullptr, 1 | 4);

    // FFN down + residual: out = X1 + h @ W2 + b2 (fp32)
    tc_gemm<<<dim3(DD/128, MR/128), thr, TC_SMEM>>>(
        h16, W2h, out, nullptr, MR, DD, FF, b2, X1, 1 | 2);
}

// round 11
// speedup vs baseline: 2.0313x; 1.0027x over previous
#include <cuda_runtime.h>
#include <cuda_fp16.h>
#include <math_constants.h>
#include <cstdint>

// Problem constants
#define BB 2
#define SS 2048
#define DD 1024
#define HH 16
#define DK 64
#define FF 4096
#define MR (BB*SS)          // 4096 rows
#define QKVN 3072

// ---------------- scratch (static device globals: alloc-free rule) ----------
__device__ __half g_nX16  [MR*DD];
__device__ __half g_qkv16 [(size_t)MR*QKVN];
__device__ __half g_ctx16 [MR*DD];
__device__ __half g_h16   [(size_t)MR*FF];
__device__ float  g_X1    [MR*DD];
__device__ __half g_Wqkv16[(size_t)DD*QKVN];   // [K=1024, N=3072]
__device__ __half g_Wo16  [DD*DD];             // [K=1024, N=1024]
__device__ __half g_W1h   [(size_t)DD*FF];     // [K=1024, N=4096]
__device__ __half g_W2h   [(size_t)FF*DD];     // [K=4096, N=1024]

// ---------------- small helpers ---------------------------------------------
__device__ __forceinline__ uint32_t smem_u32(const void* p) {
    uint32_t a;
    asm("{ .reg .u64 t; cvta.to.shared.u64 t, %1; cvt.u32.u64 %0, t; }"
        : "=r"(a) : "l"(p));
    return a;
}
__device__ __forceinline__ void cp16(uint32_t s, const void* g) {
    asm volatile("cp.async.cg.shared.global [%0], [%1], 16;" :: "r"(s), "l"(g));
}
__device__ __forceinline__ void ldsm4(uint32_t* r, uint32_t addr) {
    asm volatile(
        "ldmatrix.sync.aligned.m8n8.x4.shared.b16 {%0,%1,%2,%3}, [%4];"
        : "=r"(r[0]), "=r"(r[1]), "=r"(r[2]), "=r"(r[3]) : "r"(addr));
}
__device__ __forceinline__ void ldsm4t(uint32_t* r, uint32_t addr) {
    asm volatile(
        "ldmatrix.sync.aligned.m8n8.x4.trans.shared.b16 {%0,%1,%2,%3}, [%4];"
        : "=r"(r[0]), "=r"(r[1]), "=r"(r[2]), "=r"(r[3]) : "r"(addr));
}
__device__ __forceinline__ void mma_f16(float* c, const uint32_t* a,
                                        uint32_t b0, uint32_t b1) {
    asm volatile(
        "mma.sync.aligned.m16n8k16.row.col.f32.f16.f16.f32 "
        "{%0,%1,%2,%3}, {%4,%5,%6,%7}, {%8,%9}, {%0,%1,%2,%3};"
        : "+f"(c[0]), "+f"(c[1]), "+f"(c[2]), "+f"(c[3])
        : "r"(a[0]), "r"(a[1]), "r"(a[2]), "r"(a[3]), "r"(b0), "r"(b1));
}

// ---------------- fused weight converts (fp32 -> fp16) -----------------------
// Wq,Wk,Wv [1024,1024] -> interleaved Wqkv16 [1024, 3072]
__global__ __launch_bounds__(256)
void convert_qkv_kernel(const float* __restrict__ q, const float* __restrict__ k,
                        const float* __restrict__ v, __half* __restrict__ out)
{
    const int per = DD * DD / 4;               // float4s per matrix
    const int tot = 3 * per;
    for (int idx = blockIdx.x * 256 + threadIdx.x; idx < tot;
         idx += gridDim.x * 256) {
        const int m   = idx / per;
        const int rem = idx - m * per;
        const int r   = rem >> 8;              // DD/4 = 256 float4s per row
        const int c4  = (rem & 255) << 2;
        const float* src = (m == 0 ? q : m == 1 ? k : v) + (size_t)r * DD + c4;
        const float4 val = *(const float4*)src;
        __half2* o = (__half2*)(out + (size_t)r * QKVN + m * DD + c4);
        o[0] = __floats2half2_rn(val.x, val.y);
        o[1] = __floats2half2_rn(val.z, val.w);
    }
}

// flat converts: Wo [1024x1024], W1 [1024x4096], W2 [4096x1024]
__global__ __launch_bounds__(256)
void convert3_kernel(const float* __restrict__ a, const float* __restrict__ b,
                     const float* __restrict__ c, __half* __restrict__ oa,
                     __half* __restrict__ ob, __half* __restrict__ oc)
{
    const int na = DD * DD / 4, nb = DD * FF / 4, nc = FF * DD / 4;
    const int tot = na + nb + nc;
    for (int idx = blockIdx.x * 256 + threadIdx.x; idx < tot;
         idx += gridDim.x * 256) {
        const float* src;
        __half* dst;
        int i = idx;
        if (i < na)              { src = a; dst = oa; }
        else if ((i -= na) < nb) { src = b; dst = ob; }
        else                     { i -= nb; src = c; dst = oc; }
        const float4 val = *(const float4*)(src + (size_t)i * 4);
        __half2* o = (__half2*)(dst + (size_t)i * 4);
        o[0] = __floats2half2_rn(val.x, val.y);
        o[1] = __floats2half2_rn(val.z, val.w);
    }
}

// ---------------- LayerNorm (fp32 in, fp16 out) ------------------------------
__global__ __launch_bounds__(256)
void ln_kernel(const float* __restrict__ X, const float* __restrict__ g,
               const float* __restrict__ b, __half* __restrict__ Y)
{
    const int row = blockIdx.x;
    const int tid = threadIdx.x;
    const float4 x = ((const float4*)(X + (size_t)row * DD))[tid];

    float s  = x.x + x.y + x.z + x.w;
    float ss = x.x*x.x + x.y*x.y + x.z*x.z + x.w*x.w;
    #pragma unroll
    for (int o = 16; o; o >>= 1) {
        s  += __shfl_xor_sync(0xffffffffu, s,  o);
        ss += __shfl_xor_sync(0xffffffffu, ss, o);
    }
    __shared__ float sw[8], sw2[8];
    const int w = tid >> 5, ln = tid & 31;
    if (ln == 0) { sw[w] = s; sw2[w] = ss; }
    __syncthreads();
    float tot = 0.f, tot2 = 0.f;
    #pragma unroll
    for (int i = 0; i < 8; i++) { tot += sw[i]; tot2 += sw2[i]; }

    const float mean = tot * (1.0f / DD);
    const float var  = tot2 * (1.0f / DD) - mean * mean;
    const float rstd = rsqrtf(var + 1e-5f);

    const float4 gv = ((const float4*)g)[tid];
    const float4 bv = ((const float4*)b)[tid];
    __half2 h01 = __floats2half2_rn((x.x - mean) * rstd * gv.x + bv.x,
                                    (x.y - mean) * rstd * gv.y + bv.y);
    __half2 h23 = __floats2half2_rn((x.z - mean) * rstd * gv.z + bv.z,
                                    (x.w - mean) * rstd * gv.w + bv.w);
    __half2* yp = (__half2*)(Y + (size_t)row * DD + tid * 4);
    yp[0] = h01; yp[1] = h23;
}

// ---------------- fp16 mma.sync GEMM, B in [K,N] via ldmatrix.trans ----------
// C = A[M,K] @ B[K,N].  mode: 1=+bias, 2=+resid(fp32), 4=relu.  C16 or C out.
// CTA 128x128, warp 32x64, K-tile 64, 3-stage cp.async, 1 bar/tile, occ 2.
// Inner loop: explicit fragment double-buffering (ldsm ks+1 || mma ks).
#define AKSTR 72                                 // A smem row stride (halfs)
#define BNSTR 136                                // B smem row stride (halfs)
#define ATILEB (128 * AKSTR * 2)                 // 18432 B
#define BTILEB (64 * BNSTR * 2)                  // 17408 B
#define STGB   (ATILEB + BTILEB)                 // 35840 B
#define TC_SMEM (3 * STGB)                       // 107520 B

__global__ void __launch_bounds__(256, 2)
tc_gemm(const __half* __restrict__ A, const __half* __restrict__ B,
        float* __restrict__ C, __half* __restrict__ C16, int M, int N, int K,
        const float* __restrict__ bias, const float* __restrict__ resid,
        int mode)
{
    extern __shared__ __half smh[];
    const uint32_t sb = smem_u32(smh);

    const int tid  = threadIdx.x;
    const int wid  = tid >> 5, lane = tid & 31;
    const int tq   = lane >> 2, tr = lane & 3;
    const int wm   = (wid & 3) * 32;
    const int wn   = (wid >> 2) * 64;
    const int m0   = blockIdx.y * 128;
    const int n0   = blockIdx.x * 128;

    const int nk = K / 64;

    uint32_t a_off[2];
    #pragma unroll
    for (int mt = 0; mt < 2; mt++) {
        const int row = wm + mt * 16 + (lane & 15);
        a_off[mt] = (uint32_t)(row * AKSTR) * 2u + ((lane >> 4) << 4);
    }
    uint32_t b_off[4];
    #pragma unroll
    for (int j = 0; j < 4; j++) {
        const int col = wn + j * 16 + ((lane >> 4) << 3);
        b_off[j] = ATILEB + (uint32_t)((lane & 15) * BNSTR + col) * 2u;
    }

    float acc[2][8][4];
    #pragma unroll
    for (int mt = 0; mt < 2; mt++)
        #pragma unroll
        for (int nt = 0; nt < 8; nt++)
            #pragma unroll
            for (int i = 0; i < 4; i++) acc[mt][nt][i] = 0.f;

    auto issue_stage = [&](int kt) {
        const uint32_t sA = sb + (uint32_t)(kt % 3) * STGB;
        const uint32_t sB = sA + ATILEB;
        const int kof = kt * 64;
        #pragma unroll
        for (int l = 0; l < 4; l++) {
            const int idx = tid + l * 256;
            const int r = idx >> 3, c = idx & 7;
            cp16(sA + (uint32_t)(r * AKSTR + c * 8) * 2u,
                 A + (size_t)(m0 + r) * K + kof + c * 8);
        }
        #pragma unroll
        for (int l = 0; l < 4; l++) {
            const int idx = tid + l * 256;
            const int r = idx >> 4, c = idx & 15;
            cp16(sB + (uint32_t)(r * BNSTR + c * 8) * 2u,
                 B + (size_t)(kof + r) * N + n0 + c * 8);
        }
        asm volatile("cp.async.commit_group;" ::: "memory");
    };

    issue_stage(0);
    issue_stage(1);

    for (int kt = 0; kt < nk; kt++) {
        if (kt < nk - 1)
            asm volatile("cp.async.wait_group 1;" ::: "memory");
        else
            asm volatile("cp.async.wait_group 0;" ::: "memory");
        __syncthreads();

        if (kt + 2 < nk) issue_stage(kt + 2);

        const uint32_t stg = (uint32_t)(kt % 3) * STGB;

        // fragment double-buffer: load ks+1 while mma ks
        uint32_t a[2][2][4], bf[2][4][4];
        {
            #pragma unroll
            for (int mt = 0; mt < 2; mt++)
                ldsm4(a[0][mt], sb + a_off[mt] + stg);
            #pragma unroll
            for (int j = 0; j < 4; j++)
                ldsm4t(bf[0][j], sb + b_off[j] + stg);
        }
        #pragma unroll
        for (int ks = 0; ks < 4; ks++) {
            const int cur = ks & 1, nxt = cur ^ 1;
            if (ks < 3) {
                const uint32_t akoff = stg + (uint32_t)(ks + 1) * 32u;
                const uint32_t bkoff = stg + (uint32_t)(ks + 1) * (16u * BNSTR * 2u);
                #pragma unroll
                for (int mt = 0; mt < 2; mt++)
                    ldsm4(a[nxt][mt], sb + a_off[mt] + akoff);
                #pragma unroll
                for (int j = 0; j < 4; j++)
                    ldsm4t(bf[nxt][j], sb + b_off[j] + bkoff);
            }
            #pragma unroll
            for (int mt = 0; mt < 2; mt++)
                #pragma unroll
                for (int j = 0; j < 4; j++) {
                    mma_f16(acc[mt][2*j],   a[cur][mt], bf[cur][j][0], bf[cur][j][1]);
                    mma_f16(acc[mt][2*j+1], a[cur][mt], bf[cur][j][2], bf[cur][j][3]);
                }
        }
        __syncthreads();
    }

    #pragma unroll
    for (int mt = 0; mt < 2; mt++) {
        const int r0 = m0 + wm + mt * 16 + tq;
        #pragma unroll
        for (int half = 0; half < 2; half++) {
            const int m = r0 + half * 8;
            #pragma unroll
            for (int nt = 0; nt < 8; nt++) {
                const int n = n0 + wn + nt * 8 + tr * 2;
                float vx = acc[mt][nt][half * 2 + 0];
                float vy = acc[mt][nt][half * 2 + 1];
                if (mode & 1) {
                    const float2 bb = *(const float2*)(bias + n);
                    vx += bb.x; vy += bb.y;
                }
                if (mode & 2) {
                    const float2 rr = *(const float2*)(resid + (size_t)m * N + n);
                    vx += rr.x; vy += rr.y;
                }
                if (mode & 4) { vx = fmaxf(vx, 0.f); vy = fmaxf(vy, 0.f); }
                if (C16) {
                    *(__half2*)(C16 + (size_t)m * N + n) = __floats2half2_rn(vx, vy);
                } else {
                    float2 o; o.x = vx; o.y = vy;
                    *(float2*)(C + (size_t)m * N + n) = o;
                }
            }
        }
    }
}

// ---------------- Flash attention, fp16 tensor cores, async K/V --------------
#define ASH 72
#define KVBUFH (64 * ASH)
#define ATT_SMEM ((128*ASH + 2*KVBUFH + 2*KVBUFH + 128*ASH) * 2)   // 73728 B

__global__ __launch_bounds__(256, 2)
void attn_mma_kernel(const __half* __restrict__ QKVg, __half* __restrict__ Og,
                     int ldi)
{
    extern __shared__ __half smh[];
    __half* Qs  = smh;                       // [128][72]
    __half* Ks0 = smh + 128 * ASH;           // 2 x [64][72]
    __half* Vs0 = Ks0 + 2 * KVBUFH;          // 2 x [64][72]
    __half* Ps  = Vs0 + 2 * KVBUFH;          // [128][72]

    const int tid  = threadIdx.x;
    const int wid  = tid >> 5, lane = tid & 31;
    const int tq   = lane >> 2, tr = lane & 3;
    const int wq0  = wid * 16;
    const int bh   = blockIdx.y;
    const int b    = bh >> 4, h = bh & 15;
    const size_t base_i = (size_t)b * SS * ldi + (size_t)h * DK;
    const size_t base_o = (size_t)b * SS * DD + (size_t)h * DK;
    const int q0   = blockIdx.x * 128;

    const __half* Qg = QKVg + base_i;
    const __half* Kg = QKVg + base_i + DD;
    const __half* Vg = QKVg + base_i + 2 * DD;

    const uint32_t sQ = smem_u32(Qs);
    const uint32_t sK = smem_u32(Ks0);
    const uint32_t sV = smem_u32(Vs0);
    const uint32_t sP = smem_u32(Ps);

    const uint32_t qa = sQ + (uint32_t)((wq0 + (lane & 15)) * ASH) * 2u
                      + ((lane >> 4) << 4);
    const uint32_t pa = sP + (uint32_t)((wq0 + (lane & 15)) * ASH) * 2u
                      + ((lane >> 4) << 4);
    uint32_t ka_off[4], va_off[4];
    #pragma unroll
    for (int j = 0; j < 4; j++) {
        ka_off[j] = (uint32_t)((j * 16 + (lane & 15)) * ASH) * 2u
                  + ((lane >> 4) << 4);
        va_off[j] = (uint32_t)((lane & 15) * ASH) * 2u
                  + (uint32_t)(j * 16 + ((lane >> 4) << 3)) * 2u;
    }

    // load Q tile (scaled by exact 1/8)
    const __half2 sc2 = __float2half2_rn(0.125f);
    #pragma unroll
    for (int l = 0; l < 4; l++) {
        const int idx = tid + l * 256;
        const int r = idx >> 3, c = idx & 7;
        uint4 u = *(const uint4*)(Qg + (size_t)(q0 + r) * ldi + c * 8);
        __half2* p = (__half2*)&u;
        p[0] = __hmul2(p[0], sc2); p[1] = __hmul2(p[1], sc2);
        p[2] = __hmul2(p[2], sc2); p[3] = __hmul2(p[3], sc2);
        *(uint4*)(Qs + r * ASH + c * 8) = u;
    }

    auto issue_kv = [&](int kt) {
        const uint32_t kb_ = sK + (uint32_t)(kt & 1) * (KVBUFH * 2u);
        const uint32_t vb_ = sV + (uint32_t)(kt & 1) * (KVBUFH * 2u);
        const int kb = kt * 64;
        #pragma unroll
        for (int l = 0; l < 2; l++) {
            const int idx = tid + l * 256;
            const int r = idx >> 3, c = idx & 7;
            cp16(kb_ + (uint32_t)(r * ASH + c * 8) * 2u,
                 Kg + (size_t)(kb + r) * ldi + c * 8);
        }
        #pragma unroll
        for (int l = 0; l < 2; l++) {
            const int idx = tid + l * 256;
            const int r = idx >> 3, c = idx & 7;
            cp16(vb_ + (uint32_t)(r * ASH + c * 8) * 2u,
                 Vg + (size_t)(kb + r) * ldi + c * 8);
        }
        asm volatile("cp.async.commit_group;" ::: "memory");
    };

    issue_kv(0);

    float m_[2], l_[2], o[8][4];
    m_[0] = m_[1] = -CUDART_INF_F;
    l_[0] = l_[1] = 0.f;
    #pragma unroll
    for (int nt = 0; nt < 8; nt++)
        #pragma unroll
        for (int i = 0; i < 4; i++) o[nt][i] = 0.f;

    const int ntiles = SS / 64;
    for (int kt = 0; kt < ntiles; kt++) {
        asm volatile("cp.async.wait_group 0;" ::: "memory");
        __syncthreads();
        if (kt + 1 < ntiles) issue_kv(kt + 1);

        const uint32_t bufb = (uint32_t)(kt & 1) * (KVBUFH * 2u);

        float s[8][4];
        #pragma unroll
        for (int nt = 0; nt < 8; nt++)
            #pragma unroll
            for (int i = 0; i < 4; i++) s[nt][i] = 0.f;

        #pragma unroll
        for (int ks = 0; ks < 4; ks++) {
            const uint32_t koff = (uint32_t)ks * 32u;
            uint32_t a[4];
            ldsm4(a, qa + koff);
            #pragma unroll
            for (int j = 0; j < 4; j++) {
                uint32_t kf[4];
                ldsm4(kf, sK + bufb + ka_off[j] + koff);
                mma_f16(s[2*j],   a, kf[0], kf[2]);
                mma_f16(s[2*j+1], a, kf[1], kf[3]);
            }
        }

        #pragma unroll
        for (int half = 0; half < 2; half++) {
            float mx = -CUDART_INF_F;
            #pragma unroll
            for (int nt = 0; nt < 8; nt++)
                mx = fmaxf(mx, fmaxf(s[nt][half * 2], s[nt][half * 2 + 1]));
            mx = fmaxf(mx, __shfl_xor_sync(0xffffffffu, mx, 1));
            mx = fmaxf(mx, __shfl_xor_sync(0xffffffffu, mx, 2));
            const float mn   = fmaxf(m_[half], mx);
            const float corr = __expf(m_[half] - mn);
            m_[half] = mn;
            float sum = 0.f;
            #pragma unroll
            for (int nt = 0; nt < 8; nt++) {
                float p0 = __expf(s[nt][half * 2]     - mn);
                float p1 = __expf(s[nt][half * 2 + 1] - mn);
                s[nt][half * 2]     = p0;
                s[nt][half * 2 + 1] = p1;
                sum += p0 + p1;
            }
            sum += __shfl_xor_sync(0xffffffffu, sum, 1);
            sum += __shfl_xor_sync(0xffffffffu, sum, 2);
            l_[half] = l_[half] * corr + sum;
            #pragma unroll
            for (int nt = 0; nt < 8; nt++) {
                o[nt][half * 2]     *= corr;
                o[nt][half * 2 + 1] *= corr;
            }
        }

        #pragma unroll
        for (int nt = 0; nt < 8; nt++) {
            const int col = nt * 8 + tr * 2;
            *(__half2*)(Ps + (wq0 + tq) * ASH + col) =
                __floats2half2_rn(s[nt][0], s[nt][1]);
            *(__half2*)(Ps + (wq0 + tq + 8) * ASH + col) =
                __floats2half2_rn(s[nt][2], s[nt][3]);
        }
        __syncwarp();

        #pragma unroll
        for (int ks = 0; ks < 4; ks++) {
            uint32_t a[4];
            ldsm4(a, pa + (uint32_t)ks * 32u);
            const uint32_t voff = bufb + (uint32_t)ks * (16u * ASH * 2u);
            #pragma unroll
            for (int j = 0; j < 4; j++) {
                uint32_t vf[4];
                ldsm4t(vf, sV + voff + va_off[j]);
                mma_f16(o[2*j],   a, vf[0], vf[1]);
                mma_f16(o[2*j+1], a, vf[2], vf[3]);
            }
        }
    }

    const float inv0 = 1.0f / l_[0];
    const float inv1 = 1.0f / l_[1];
    #pragma unroll
    for (int nt = 0; nt < 8; nt++) {
        const int col = nt * 8 + tr * 2;
        *(__half2*)(Og + base_o + (size_t)(q0 + wq0 + tq) * DD + col) =
            __floats2half2_rn(o[nt][0] * inv0, o[nt][1] * inv0);
        *(__half2*)(Og + base_o + (size_t)(q0 + wq0 + tq + 8) * DD + col) =
            __floats2half2_rn(o[nt][2] * inv1, o[nt][3] * inv1);
    }
}

// ---------------- launch -----------------------------------------------------
extern "C" void kernel_launch(void* const* d_in, const int* in_sizes, int n_in,
                              void* d_out, int out_size)
{
    const float* X   = (const float*)d_in[0];
    const float* Wq  = (const float*)d_in[1];
    const float* Wk  = (const float*)d_in[2];
    const float* Wv  = (const float*)d_in[3];
    const float* Wo  = (const float*)d_in[4];
    const float* W1  = (const float*)d_in[5];
    const float* b1  = (const float*)d_in[6];
    const float* W2  = (const float*)d_in[7];
    const float* b2  = (const float*)d_in[8];
    const float* g1  = (const float*)d_in[9];
    const float* be1 = (const float*)d_in[10];
    const float* g2  = (const float*)d_in[11];
    const float* be2 = (const float*)d_in[12];
    float* out = (float*)d_out;

    __half *nX16, *qkv16, *ctx16, *h16, *Wqkv16, *Wo16, *W1h, *W2h;
    float *X1;
    cudaGetSymbolAddress((void**)&nX16,   g_nX16);
    cudaGetSymbolAddress((void**)&qkv16,  g_qkv16);
    cudaGetSymbolAddress((void**)&ctx16,  g_ctx16);
    cudaGetSymbolAddress((void**)&h16,    g_h16);
    cudaGetSymbolAddress((void**)&X1,     g_X1);
    cudaGetSymbolAddress((void**)&Wqkv16, g_Wqkv16);
    cudaGetSymbolAddress((void**)&Wo16,   g_Wo16);
    cudaGetSymbolAddress((void**)&W1h,    g_W1h);
    cudaGetSymbolAddress((void**)&W2h,    g_W2h);

    cudaFuncSetAttribute(tc_gemm, cudaFuncAttributeMaxDynamicSharedMemorySize,
                         TC_SMEM);
    cudaFuncSetAttribute(attn_mma_kernel,
                         cudaFuncAttributeMaxDynamicSharedMemorySize, ATT_SMEM);

    dim3 thr(256);

    // 1-2: fused weight converts
    convert_qkv_kernel<<<1024, thr>>>(Wq, Wk, Wv, Wqkv16);
    convert3_kernel<<<2048, thr>>>(Wo, W1, W2, Wo16, W1h, W2h);

    // 3: LN1
    ln_kernel<<<MR, thr>>>(X, g1, be1, nX16);

    // 4: fused QKV projection (profiled launch)
    tc_gemm<<<dim3(QKVN/128, MR/128), thr, TC_SMEM>>>(
        nX16, Wqkv16, nullptr, qkv16, MR, QKVN, DD, nullptr, nullptr, 0);

    // 5: attention
    attn_mma_kernel<<<dim3(SS/128, BB*HH), thr, ATT_SMEM>>>(qkv16, ctx16, QKVN);

    // 6: output projection + residual -> X1 fp32
    tc_gemm<<<dim3(DD/128, MR/128), thr, TC_SMEM>>>(
        ctx16, Wo16, X1, nullptr, MR, DD, DD, nullptr, X, 2);

    // 7: LN2
    ln_kernel<<<MR, thr>>>(X1, g2, be2, nX16);

    // 8: FFN up
    tc_gemm<<<dim3(FF/128, MR/128), thr, TC_SMEM>>>(
        nX16, W1h, nullptr, h16, MR, FF, DD, b1, nullptr, 1 | 4);

    // 9: FFN down + residual
    tc_gemm<<<dim3(DD/128, MR/128), thr, TC_SMEM>>>(
        h16, W2h, out, nullptr, MR, DD, FF, b2, X1, 1 | 2);
}